// round 1
// baseline (speedup 1.0000x reference)
#include <cuda_runtime.h>
#include <cstdint>

#define B_ 2
#define L_ 4800
#define S_ 4800
#define C_ 256
#define NT_ 38          // ceil(4800/128)
#define SMPAD 36        // 32 + 4 pad (floats) per smem row

// ---------------- scratch (device globals: no allocs allowed) ----------------
__device__ float g_f0[B_ * L_ * C_];
__device__ float g_f1[B_ * S_ * C_];
__device__ float g_sim[(size_t)B_ * L_ * S_];          // 184 MB
__device__ float g_rmax_p[B_ * L_ * NT_];
__device__ float g_rsum_p[B_ * L_ * NT_];
__device__ float g_cmax_p[B_ * S_ * NT_];
__device__ float g_csum_p[B_ * S_ * NT_];
__device__ float g_rmax[B_ * L_];
__device__ float g_rsum[B_ * L_];
__device__ float g_cmax[B_ * S_];
__device__ float g_csum[B_ * S_];

__device__ __forceinline__ float tf32r(float x) {
    uint32_t u = __float_as_uint(x);
    asm("cvt.rna.tf32.f32 %0, %0;" : "+r"(u));
    return __uint_as_float(u);
}

__device__ __forceinline__ void mma8(float d[4], const uint32_t a[4], const uint32_t b[2]) {
    asm volatile(
        "mma.sync.aligned.m16n8k8.row.col.f32.tf32.tf32.f32 "
        "{%0,%1,%2,%3}, {%4,%5,%6,%7}, {%8,%9}, {%0,%1,%2,%3};"
        : "+f"(d[0]), "+f"(d[1]), "+f"(d[2]), "+f"(d[3])
        : "r"(a[0]), "r"(a[1]), "r"(a[2]), "r"(a[3]), "r"(b[0]), "r"(b[1]));
}

__device__ __forceinline__ float neginf() { return __int_as_float(0xff800000); }

// ---------------- shared GEMM-NT mainloop ----------------
// C[128,128] tile of A[M,K=256] (row-major) x Bm[N,K=256] (row-major, i.e. B^T)
// block = 256 threads, warps 2(M) x 4(N), warp tile 64x32, mma m16n8k8 tf32.
template <bool GUARD>
__device__ __forceinline__ void gemm_mainloop(
    const float* __restrict__ A, const float* __restrict__ Bm,
    int m0, int n0, int Mrows, int Nrows,
    float* As, float* Bs, float acc[4][4][4])
{
    const int tid  = threadIdx.x;
    const int lane = tid & 31;
    const int warp = tid >> 5;
    const int wm = warp >> 2, wn = warp & 3;
    const int gp = lane >> 2, tg = lane & 3;

    for (int kc = 0; kc < C_; kc += 32) {
        // gmem -> smem (tf32-round on the way in; idempotent on pre-rounded data)
        #pragma unroll
        for (int i = 0; i < 4; i++) {
            int idx = tid + i * 256;
            int r   = idx >> 3;
            int kq  = (idx & 7) * 4;
            float4 va = make_float4(0.f, 0.f, 0.f, 0.f);
            int gr = m0 + r;
            if (!GUARD || gr < Mrows)
                va = *reinterpret_cast<const float4*>(A + (size_t)gr * C_ + kc + kq);
            va.x = tf32r(va.x); va.y = tf32r(va.y); va.z = tf32r(va.z); va.w = tf32r(va.w);
            *reinterpret_cast<float4*>(As + r * SMPAD + kq) = va;

            float4 vb = make_float4(0.f, 0.f, 0.f, 0.f);
            int gn = n0 + r;
            if (!GUARD || gn < Nrows)
                vb = *reinterpret_cast<const float4*>(Bm + (size_t)gn * C_ + kc + kq);
            vb.x = tf32r(vb.x); vb.y = tf32r(vb.y); vb.z = tf32r(vb.z); vb.w = tf32r(vb.w);
            *reinterpret_cast<float4*>(Bs + r * SMPAD + kq) = vb;
        }
        __syncthreads();

        #pragma unroll
        for (int ks = 0; ks < 4; ks++) {
            const int k0 = ks * 8;
            uint32_t afr[4][4];
            uint32_t bfr[4][2];
            #pragma unroll
            for (int mf = 0; mf < 4; mf++) {
                const float* p = As + (wm * 64 + mf * 16 + gp) * SMPAD + k0 + tg;
                afr[mf][0] = __float_as_uint(p[0]);
                afr[mf][1] = __float_as_uint(p[8 * SMPAD]);
                afr[mf][2] = __float_as_uint(p[4]);
                afr[mf][3] = __float_as_uint(p[8 * SMPAD + 4]);
            }
            #pragma unroll
            for (int nf = 0; nf < 4; nf++) {
                const float* p = Bs + (wn * 32 + nf * 8 + gp) * SMPAD + k0 + tg;
                bfr[nf][0] = __float_as_uint(p[0]);
                bfr[nf][1] = __float_as_uint(p[4]);
            }
            #pragma unroll
            for (int mf = 0; mf < 4; mf++)
                #pragma unroll
                for (int nf = 0; nf < 4; nf++)
                    mma8(acc[mf][nf], afr[mf], bfr[nf]);
        }
        __syncthreads();
    }
}

// ---------------- pass 1: projection f = (X @ W^T + b) / 16 ----------------
__global__ __launch_bounds__(256) void proj_kernel(
    const float* __restrict__ X, const float* __restrict__ W,
    const float* __restrict__ bias, int which)
{
    __shared__ float As[128 * SMPAD];
    __shared__ float Bs[128 * SMPAD];
    float acc[4][4][4] = {};

    const int n0 = blockIdx.x * 128;
    const int m0 = blockIdx.y * 128;
    gemm_mainloop<false>(X, W, m0, n0, B_ * L_, C_, As, Bs, acc);

    float* O = which ? g_f1 : g_f0;
    const int tid = threadIdx.x, lane = tid & 31, warp = tid >> 5;
    const int wm = warp >> 2, wn = warp & 3, gp = lane >> 2, tg = lane & 3;

    #pragma unroll
    for (int mf = 0; mf < 4; mf++) {
        int row = m0 + wm * 64 + mf * 16 + gp;
        #pragma unroll
        for (int nf = 0; nf < 4; nf++) {
            int col = n0 + wn * 32 + nf * 8 + 2 * tg;
            float b0 = __ldg(bias + col), b1 = __ldg(bias + col + 1);
            #pragma unroll
            for (int h = 0; h < 2; h++) {
                float2 v;
                v.x = (acc[mf][nf][2 * h]     + b0) * 0.0625f;
                v.y = (acc[mf][nf][2 * h + 1] + b1) * 0.0625f;
                *reinterpret_cast<float2*>(O + (size_t)(row + 8 * h) * C_ + col) = v;
            }
        }
    }
}

// ---------------- pass 2: sim tile + per-tile row/col (max, sum exp) ----------------
__global__ __launch_bounds__(256) void sim_kernel()
{
    __shared__ float As[128 * SMPAD];
    __shared__ float Bs[128 * SMPAD];
    __shared__ float red_m[4 * 128];
    __shared__ float red_s[4 * 128];
    __shared__ float redc_m[2 * 128];
    __shared__ float redc_s[2 * 128];

    const int tn = blockIdx.x, tm = blockIdx.y, bb = blockIdx.z;
    const int n0 = tn * 128, m0 = tm * 128;

    float acc[4][4][4] = {};
    gemm_mainloop<true>(g_f0 + (size_t)bb * L_ * C_, g_f1 + (size_t)bb * S_ * C_,
                        m0, n0, L_, S_, As, Bs, acc);

    const int tid = threadIdx.x, lane = tid & 31, warp = tid >> 5;
    const int wm = warp >> 2, wn = warp & 3, gp = lane >> 2, tg = lane & 3;

    // logits = dot / TEMPERATURE  (f0,f1 already carry the 1/sqrt(C) each)
    #pragma unroll
    for (int mf = 0; mf < 4; mf++)
        #pragma unroll
        for (int nf = 0; nf < 4; nf++)
            #pragma unroll
            for (int e = 0; e < 4; e++)
                acc[mf][nf][e] *= 10.0f;

    // store sim (fp32, bit-exact source for later max-equality test)
    #pragma unroll
    for (int mf = 0; mf < 4; mf++)
        #pragma unroll
        for (int h = 0; h < 2; h++) {
            int row = m0 + wm * 64 + mf * 16 + 8 * h + gp;
            if (row < L_) {
                #pragma unroll
                for (int nf = 0; nf < 4; nf++) {
                    int s = n0 + wn * 32 + nf * 8 + 2 * tg;
                    if (s < S_) {
                        float2 v = make_float2(acc[mf][nf][2 * h], acc[mf][nf][2 * h + 1]);
                        *reinterpret_cast<float2*>(&g_sim[((size_t)bb * L_ + row) * S_ + s]) = v;
                    }
                }
            }
        }

    // ---- row partials: max & sum(exp(x)) over this tile's 128 cols ----
    #pragma unroll
    for (int mf = 0; mf < 4; mf++)
        #pragma unroll
        for (int h = 0; h < 2; h++) {
            float m = neginf(), sm = 0.f;
            #pragma unroll
            for (int nf = 0; nf < 4; nf++)
                #pragma unroll
                for (int ch = 0; ch < 2; ch++) {
                    int s = n0 + wn * 32 + nf * 8 + 2 * tg + ch;
                    if (s < S_) {
                        float v = acc[mf][nf][2 * h + ch];
                        m = fmaxf(m, v);
                        sm += __expf(v);
                    }
                }
            m  = fmaxf(m, __shfl_xor_sync(0xffffffffu, m, 1));
            m  = fmaxf(m, __shfl_xor_sync(0xffffffffu, m, 2));
            sm += __shfl_xor_sync(0xffffffffu, sm, 1);
            sm += __shfl_xor_sync(0xffffffffu, sm, 2);
            if (tg == 0) {
                int rib = wm * 64 + mf * 16 + 8 * h + gp;
                red_m[wn * 128 + rib] = m;
                red_s[wn * 128 + rib] = sm;
            }
        }
    __syncthreads();

    // ---- col partials: max & sum(exp(x)) over this tile's 128 rows ----
    #pragma unroll
    for (int nf = 0; nf < 4; nf++)
        #pragma unroll
        for (int ch = 0; ch < 2; ch++) {
            float m = neginf(), sm = 0.f;
            #pragma unroll
            for (int mf = 0; mf < 4; mf++)
                #pragma unroll
                for (int h = 0; h < 2; h++) {
                    int row = m0 + wm * 64 + mf * 16 + 8 * h + gp;
                    if (row < L_) {
                        float v = acc[mf][nf][2 * h + ch];
                        m = fmaxf(m, v);
                        sm += __expf(v);
                    }
                }
            m  = fmaxf(m, __shfl_xor_sync(0xffffffffu, m, 4));
            m  = fmaxf(m, __shfl_xor_sync(0xffffffffu, m, 8));
            m  = fmaxf(m, __shfl_xor_sync(0xffffffffu, m, 16));
            sm += __shfl_xor_sync(0xffffffffu, sm, 4);
            sm += __shfl_xor_sync(0xffffffffu, sm, 8);
            sm += __shfl_xor_sync(0xffffffffu, sm, 16);
            if (gp == 0) {
                int cib = wn * 32 + nf * 8 + 2 * tg + ch;
                redc_m[wm * 128 + cib] = m;
                redc_s[wm * 128 + cib] = sm;
            }
        }

    // merge the 4 n-warp row partials (red_* written before first sync)
    if (tid < 128) {
        float m = red_m[tid], sm = red_s[tid];
        #pragma unroll
        for (int j = 1; j < 4; j++) {
            m  = fmaxf(m, red_m[j * 128 + tid]);
            sm += red_s[j * 128 + tid];
        }
        int gl = m0 + tid;
        if (gl < L_) {
            int o = (bb * L_ + gl) * NT_ + tn;
            g_rmax_p[o] = m;
            g_rsum_p[o] = sm;
        }
    }
    __syncthreads();

    // merge the 2 m-warp col partials
    if (tid < 128) {
        float m  = fmaxf(redc_m[tid], redc_m[128 + tid]);
        float sm = redc_s[tid] + redc_s[128 + tid];
        int gs = n0 + tid;
        if (gs < S_) {
            int o = (bb * S_ + gs) * NT_ + tm;
            g_cmax_p[o] = m;
            g_csum_p[o] = sm;
        }
    }
}

// ---------------- pass 3: reduce tile partials ----------------
__global__ __launch_bounds__(256) void reduce_stats_kernel()
{
    int i = blockIdx.x * blockDim.x + threadIdx.x;
    if (i < B_ * L_) {
        float m = neginf(), s = 0.f;
        #pragma unroll
        for (int t = 0; t < NT_; t++) {
            m = fmaxf(m, g_rmax_p[i * NT_ + t]);
            s += g_rsum_p[i * NT_ + t];
        }
        g_rmax[i] = m;
        g_rsum[i] = s;
    } else if (i < 2 * B_ * L_) {   // L_ == S_
        int j = i - B_ * L_;
        float m = neginf(), s = 0.f;
        #pragma unroll
        for (int t = 0; t < NT_; t++) {
            m = fmaxf(m, g_cmax_p[j * NT_ + t]);
            s += g_csum_p[j * NT_ + t];
        }
        g_cmax[j] = m;
        g_csum[j] = s;
    }
}

// ---------------- pass 4: conf planes + mask + mconf ----------------
__global__ __launch_bounds__(256) void finalize_kernel(
    const int* __restrict__ ph0, const int* __restrict__ pw0,
    const int* __restrict__ ph1, const int* __restrict__ pw1,
    float* __restrict__ out)
{
    const int NS4 = S_ / 4;
    int t = blockIdx.x * blockDim.x + threadIdx.x;
    if (t >= B_ * L_ * NS4) return;

    int s0  = (t % NS4) * 4;
    int rem = t / NS4;
    int l   = rem % L_;
    int bb  = rem / L_;

    int h0 = __ldg(ph0), w0 = __ldg(pw0), h1 = __ldg(ph1), w1 = __ldg(pw1);
    int i0 = l / w0, j0 = l - i0 * w0;
    bool in0 = (i0 >= 2) && (i0 < h0 - 2) && (j0 >= 2) && (j0 < w0 - 2);

    size_t base = ((size_t)bb * L_ + l) * S_ + s0;
    float4 xv  = *reinterpret_cast<const float4*>(g_sim + base);
    float rm   = g_rmax[bb * L_ + l];
    float rinv = 1.0f / g_rsum[bb * L_ + l];
    float4 cm4 = *reinterpret_cast<const float4*>(g_cmax + bb * S_ + s0);
    float4 cs4 = *reinterpret_cast<const float4*>(g_csum + bb * S_ + s0);

    float c01v[4], c10v[4], mcv[4];
    const float xs[4]  = {xv.x, xv.y, xv.z, xv.w};
    const float cms[4] = {cm4.x, cm4.y, cm4.z, cm4.w};
    const float css[4] = {cs4.x, cs4.y, cs4.z, cs4.w};

    #pragma unroll
    for (int e = 0; e < 4; e++) {
        int   s   = s0 + e;
        float X   = xs[e];
        float E   = __expf(X);
        float c01 = E * rinv;
        float c10 = __fdividef(E, css[e]);
        int i1 = s / w1, j1 = s - i1 * w1;
        bool in1 = (i1 >= 2) && (i1 < h1 - 2) && (j1 >= 2) && (j1 < w1 - 2);
        bool mk  = in0 && in1 &&
                   ((c01 > 0.2f && X == rm) || (c10 > 0.2f && X == cms[e]));
        c01v[e] = c01;
        c10v[e] = c10;
        mcv[e]  = mk ? fmaxf(c01, c10) : 0.f;
    }

    const size_t P = (size_t)B_ * L_ * S_;
    *reinterpret_cast<float4*>(out + base)         = make_float4(c01v[0], c01v[1], c01v[2], c01v[3]);
    *reinterpret_cast<float4*>(out + P + base)     = make_float4(c10v[0], c10v[1], c10v[2], c10v[3]);
    *reinterpret_cast<float4*>(out + 2 * P + base) = make_float4(mcv[0],  mcv[1],  mcv[2],  mcv[3]);
}

// ---------------- launch ----------------
extern "C" void kernel_launch(void* const* d_in, const int* in_sizes, int n_in,
                              void* d_out, int out_size)
{
    const float* feat0 = (const float*)d_in[0];
    const float* feat1 = (const float*)d_in[1];
    const float* W     = (const float*)d_in[2];
    const float* bias  = (const float*)d_in[3];
    const int*   h0    = (const int*)d_in[4];
    const int*   w0    = (const int*)d_in[5];
    const int*   h1    = (const int*)d_in[6];
    const int*   w1    = (const int*)d_in[7];
    float* out = (float*)d_out;

    proj_kernel<<<dim3(2, 75, 1), 256>>>(feat0, W, bias, 0);
    proj_kernel<<<dim3(2, 75, 1), 256>>>(feat1, W, bias, 1);
    sim_kernel<<<dim3(NT_, NT_, B_), 256>>>();
    reduce_stats_kernel<<<(2 * B_ * L_ + 255) / 256, 256>>>();
    finalize_kernel<<<(B_ * L_ * (S_ / 4) + 255) / 256, 256>>>(h0, w0, h1, w1, out);
}

// round 2
// speedup vs baseline: 1.6449x; 1.6449x over previous
#include <cuda_runtime.h>
#include <cstdint>

#define B_ 2
#define L_ 4800
#define S_ 4800
#define C_ 256
#define NT_ 38          // ceil(4800/128)
#define SMPAD 36        // 32 + 4 pad (floats) per smem row
#define STAGE_F (2 * 128 * SMPAD)   // floats per pipeline stage (A tile + B tile)

// ---------------- scratch (device globals: no allocs allowed) ----------------
__device__ float g_f0[B_ * L_ * C_];
__device__ float g_f1[B_ * S_ * C_];
__device__ float g_sim[(size_t)B_ * L_ * S_];          // stores E = exp(logit)
__device__ float g_rmax_p[NT_ * B_ * L_];
__device__ float g_rsum_p[NT_ * B_ * L_];
__device__ float g_cmax_p[NT_ * B_ * S_];
__device__ float g_csum_p[NT_ * B_ * S_];
__device__ float g_rmax[B_ * L_];
__device__ float g_rsum[B_ * L_];
__device__ float g_cmax[B_ * S_];
__device__ float g_csum[B_ * S_];

__device__ __forceinline__ float tf32r(float x) {
    uint32_t u = __float_as_uint(x);
    asm("cvt.rna.tf32.f32 %0, %0;" : "+r"(u));
    return __uint_as_float(u);
}

__device__ __forceinline__ void mma8(float d[4], const uint32_t a[4], const uint32_t b[2]) {
    asm volatile(
        "mma.sync.aligned.m16n8k8.row.col.f32.tf32.tf32.f32 "
        "{%0,%1,%2,%3}, {%4,%5,%6,%7}, {%8,%9}, {%0,%1,%2,%3};"
        : "+f"(d[0]), "+f"(d[1]), "+f"(d[2]), "+f"(d[3])
        : "r"(a[0]), "r"(a[1]), "r"(a[2]), "r"(a[3]), "r"(b[0]), "r"(b[1]));
}

__device__ __forceinline__ float neginf() { return __int_as_float(0xff800000); }

__device__ __forceinline__ uint32_t smaddr(const void* p) {
    return (uint32_t)__cvta_generic_to_shared(p);
}

#define CP16(dst, src, pred)                                                   \
    asm volatile("cp.async.cg.shared.global [%0], [%1], 16, %2;\n" ::          \
                     "r"(dst), "l"(src), "r"((pred) ? 16 : 0))

// ================= proj: f = round_tf32((X @ W^T + b) / 16) =================
// non-pipelined static-smem GEMM (tiny: 2 x 5 us)
__device__ __forceinline__ void proj_mainloop(
    const float* __restrict__ A, const float* __restrict__ Bm,
    int m0, int n0, float* As, float* Bs, float acc[4][4][4])
{
    const int tid  = threadIdx.x;
    const int lane = tid & 31;
    const int warp = tid >> 5;
    const int wm = warp >> 2, wn = warp & 3;
    const int gp = lane >> 2, tg = lane & 3;

    for (int kc = 0; kc < C_; kc += 32) {
        #pragma unroll
        for (int i = 0; i < 4; i++) {
            int idx = tid + i * 256;
            int r   = idx >> 3;
            int kq  = (idx & 7) * 4;
            float4 va = *reinterpret_cast<const float4*>(A + (size_t)(m0 + r) * C_ + kc + kq);
            va.x = tf32r(va.x); va.y = tf32r(va.y); va.z = tf32r(va.z); va.w = tf32r(va.w);
            *reinterpret_cast<float4*>(As + r * SMPAD + kq) = va;
            float4 vb = *reinterpret_cast<const float4*>(Bm + (size_t)(n0 + r) * C_ + kc + kq);
            vb.x = tf32r(vb.x); vb.y = tf32r(vb.y); vb.z = tf32r(vb.z); vb.w = tf32r(vb.w);
            *reinterpret_cast<float4*>(Bs + r * SMPAD + kq) = vb;
        }
        __syncthreads();
        #pragma unroll
        for (int ks = 0; ks < 4; ks++) {
            const int k0 = ks * 8;
            uint32_t afr[4][4];
            uint32_t bfr[4][2];
            #pragma unroll
            for (int mf = 0; mf < 4; mf++) {
                const float* p = As + (wm * 64 + mf * 16 + gp) * SMPAD + k0 + tg;
                afr[mf][0] = __float_as_uint(p[0]);
                afr[mf][1] = __float_as_uint(p[8 * SMPAD]);
                afr[mf][2] = __float_as_uint(p[4]);
                afr[mf][3] = __float_as_uint(p[8 * SMPAD + 4]);
            }
            #pragma unroll
            for (int nf = 0; nf < 4; nf++) {
                const float* p = Bs + (wn * 32 + nf * 8 + gp) * SMPAD + k0 + tg;
                bfr[nf][0] = __float_as_uint(p[0]);
                bfr[nf][1] = __float_as_uint(p[4]);
            }
            #pragma unroll
            for (int mf = 0; mf < 4; mf++)
                #pragma unroll
                for (int nf = 0; nf < 4; nf++)
                    mma8(acc[mf][nf], afr[mf], bfr[nf]);
        }
        __syncthreads();
    }
}

__global__ __launch_bounds__(256) void proj_kernel(
    const float* __restrict__ X, const float* __restrict__ W,
    const float* __restrict__ bias, int which)
{
    __shared__ float As[128 * SMPAD];
    __shared__ float Bs[128 * SMPAD];
    float acc[4][4][4] = {};

    const int n0 = blockIdx.x * 128;
    const int m0 = blockIdx.y * 128;
    proj_mainloop(X, W, m0, n0, As, Bs, acc);

    float* O = which ? g_f1 : g_f0;
    const int tid = threadIdx.x, lane = tid & 31, warp = tid >> 5;
    const int wm = warp >> 2, wn = warp & 3, gp = lane >> 2, tg = lane & 3;

    #pragma unroll
    for (int mf = 0; mf < 4; mf++) {
        int row = m0 + wm * 64 + mf * 16 + gp;
        #pragma unroll
        for (int nf = 0; nf < 4; nf++) {
            int col = n0 + wn * 32 + nf * 8 + 2 * tg;
            float b0 = __ldg(bias + col), b1 = __ldg(bias + col + 1);
            #pragma unroll
            for (int h = 0; h < 2; h++) {
                float2 v;
                // pre-round to tf32: sim pass copies raw bytes via cp.async
                v.x = tf32r((acc[mf][nf][2 * h]     + b0) * 0.0625f);
                v.y = tf32r((acc[mf][nf][2 * h + 1] + b1) * 0.0625f);
                *reinterpret_cast<float2*>(O + (size_t)(row + 8 * h) * C_ + col) = v;
            }
        }
    }
}

// ======== sim: E=exp(logit) tile + per-tile row/col (max, sum) of E ========
__global__ __launch_bounds__(256, 2) void sim_kernel()
{
    extern __shared__ float sm[];
    __shared__ float red_m[4 * 128];
    __shared__ float red_s[4 * 128];
    __shared__ float redc_m[2 * 128];
    __shared__ float redc_s[2 * 128];

    const int tn = blockIdx.x, tm = blockIdx.y, bb = blockIdx.z;
    const int n0 = tn * 128, m0 = tm * 128;
    const float* A  = g_f0 + (size_t)bb * L_ * C_;
    const float* Bm = g_f1 + (size_t)bb * S_ * C_;

    const int tid  = threadIdx.x;
    const int lane = tid & 31;
    const int warp = tid >> 5;
    const int wm = warp >> 2, wn = warp & 3;
    const int gp = lane >> 2, tg = lane & 3;
    const int cr = tid >> 3, ckq = (tid & 7) * 4;

    float acc[4][4][4] = {};

    // ---- prefetch chunk 0 ----
    {
        float* As = sm;
        float* Bs = sm + 128 * SMPAD;
        #pragma unroll
        for (int i = 0; i < 4; i++) {
            int r = cr + i * 32;
            int gr = m0 + r; bool oa = gr < L_;
            CP16(smaddr(As + r * SMPAD + ckq), A + (size_t)(oa ? gr : 0) * C_ + ckq, oa);
            int gn = n0 + r; bool ob = gn < S_;
            CP16(smaddr(Bs + r * SMPAD + ckq), Bm + (size_t)(ob ? gn : 0) * C_ + ckq, ob);
        }
        asm volatile("cp.async.commit_group;\n");
    }

    #pragma unroll
    for (int c = 0; c < 8; c++) {
        if (c < 7) {
            const int kc = (c + 1) * 32;
            float* As = sm + ((c + 1) & 1) * STAGE_F;
            float* Bs = As + 128 * SMPAD;
            #pragma unroll
            for (int i = 0; i < 4; i++) {
                int r = cr + i * 32;
                int gr = m0 + r; bool oa = gr < L_;
                CP16(smaddr(As + r * SMPAD + ckq), A + (size_t)(oa ? gr : 0) * C_ + kc + ckq, oa);
                int gn = n0 + r; bool ob = gn < S_;
                CP16(smaddr(Bs + r * SMPAD + ckq), Bm + (size_t)(ob ? gn : 0) * C_ + kc + ckq, ob);
            }
            asm volatile("cp.async.commit_group;\n");
            asm volatile("cp.async.wait_group 1;\n");
        } else {
            asm volatile("cp.async.wait_group 0;\n");
        }
        __syncthreads();

        const float* As = sm + (c & 1) * STAGE_F;
        const float* Bs = As + 128 * SMPAD;
        #pragma unroll
        for (int ks = 0; ks < 4; ks++) {
            const int k0 = ks * 8;
            uint32_t afr[4][4];
            uint32_t bfr[4][2];
            #pragma unroll
            for (int mf = 0; mf < 4; mf++) {
                const float* p = As + (wm * 64 + mf * 16 + gp) * SMPAD + k0 + tg;
                afr[mf][0] = __float_as_uint(p[0]);
                afr[mf][1] = __float_as_uint(p[8 * SMPAD]);
                afr[mf][2] = __float_as_uint(p[4]);
                afr[mf][3] = __float_as_uint(p[8 * SMPAD + 4]);
            }
            #pragma unroll
            for (int nf = 0; nf < 4; nf++) {
                const float* p = Bs + (wn * 32 + nf * 8 + gp) * SMPAD + k0 + tg;
                bfr[nf][0] = __float_as_uint(p[0]);
                bfr[nf][1] = __float_as_uint(p[4]);
            }
            #pragma unroll
            for (int mf = 0; mf < 4; mf++)
                #pragma unroll
                for (int nf = 0; nf < 4; nf++)
                    mma8(acc[mf][nf], afr[mf], bfr[nf]);
        }
        __syncthreads();
    }

    // ---- transform in place: acc := E = exp(logit) ----
    #pragma unroll
    for (int mf = 0; mf < 4; mf++)
        #pragma unroll
        for (int nf = 0; nf < 4; nf++)
            #pragma unroll
            for (int e = 0; e < 4; e++)
                acc[mf][nf][e] = __expf(acc[mf][nf][e] * 10.0f);

    // ---- store E ----
    #pragma unroll
    for (int mf = 0; mf < 4; mf++)
        #pragma unroll
        for (int h = 0; h < 2; h++) {
            int row = m0 + wm * 64 + mf * 16 + 8 * h + gp;
            if (row < L_) {
                #pragma unroll
                for (int nf = 0; nf < 4; nf++) {
                    int s = n0 + wn * 32 + nf * 8 + 2 * tg;
                    if (s < S_) {
                        float2 v = make_float2(acc[mf][nf][2 * h], acc[mf][nf][2 * h + 1]);
                        *reinterpret_cast<float2*>(&g_sim[((size_t)bb * L_ + row) * S_ + s]) = v;
                    }
                }
            }
        }

    // ---- row partials over this tile's 128 cols ----
    #pragma unroll
    for (int mf = 0; mf < 4; mf++)
        #pragma unroll
        for (int h = 0; h < 2; h++) {
            float m = neginf(), smm = 0.f;
            #pragma unroll
            for (int nf = 0; nf < 4; nf++)
                #pragma unroll
                for (int ch = 0; ch < 2; ch++) {
                    int s = n0 + wn * 32 + nf * 8 + 2 * tg + ch;
                    if (s < S_) {
                        float v = acc[mf][nf][2 * h + ch];
                        m = fmaxf(m, v);
                        smm += v;
                    }
                }
            m   = fmaxf(m, __shfl_xor_sync(0xffffffffu, m, 1));
            m   = fmaxf(m, __shfl_xor_sync(0xffffffffu, m, 2));
            smm += __shfl_xor_sync(0xffffffffu, smm, 1);
            smm += __shfl_xor_sync(0xffffffffu, smm, 2);
            if (tg == 0) {
                int rib = wm * 64 + mf * 16 + 8 * h + gp;
                red_m[wn * 128 + rib] = m;
                red_s[wn * 128 + rib] = smm;
            }
        }
    __syncthreads();

    // ---- col partials over this tile's 128 rows ----
    #pragma unroll
    for (int nf = 0; nf < 4; nf++)
        #pragma unroll
        for (int ch = 0; ch < 2; ch++) {
            float m = neginf(), smm = 0.f;
            #pragma unroll
            for (int mf = 0; mf < 4; mf++)
                #pragma unroll
                for (int h = 0; h < 2; h++) {
                    int row = m0 + wm * 64 + mf * 16 + 8 * h + gp;
                    if (row < L_) {
                        float v = acc[mf][nf][2 * h + ch];
                        m = fmaxf(m, v);
                        smm += v;
                    }
                }
            m   = fmaxf(m, __shfl_xor_sync(0xffffffffu, m, 4));
            m   = fmaxf(m, __shfl_xor_sync(0xffffffffu, m, 8));
            m   = fmaxf(m, __shfl_xor_sync(0xffffffffu, m, 16));
            smm += __shfl_xor_sync(0xffffffffu, smm, 4);
            smm += __shfl_xor_sync(0xffffffffu, smm, 8);
            smm += __shfl_xor_sync(0xffffffffu, smm, 16);
            if (gp == 0) {
                int cib = wn * 32 + nf * 8 + 2 * tg + ch;
                redc_m[wm * 128 + cib] = m;
                redc_s[wm * 128 + cib] = smm;
            }
        }

    // merge the 4 n-warp row partials; write transposed [tile][row]
    if (tid < 128) {
        float m = red_m[tid], smm = red_s[tid];
        #pragma unroll
        for (int j = 1; j < 4; j++) {
            m   = fmaxf(m, red_m[j * 128 + tid]);
            smm += red_s[j * 128 + tid];
        }
        int gl = m0 + tid;
        if (gl < L_) {
            size_t o = (size_t)tn * (B_ * L_) + bb * L_ + gl;
            g_rmax_p[o] = m;
            g_rsum_p[o] = smm;
        }
    }
    __syncthreads();

    // merge the 2 m-warp col partials; write transposed [tile][col]
    if (tid < 128) {
        float m   = fmaxf(redc_m[tid], redc_m[128 + tid]);
        float smm = redc_s[tid] + redc_s[128 + tid];
        int gs = n0 + tid;
        if (gs < S_) {
            size_t o = (size_t)tm * (B_ * S_) + bb * S_ + gs;
            g_cmax_p[o] = m;
            g_csum_p[o] = smm;
        }
    }
}

// ---------------- pass 3: reduce tile partials (coalesced) ----------------
__global__ __launch_bounds__(256) void reduce_stats_kernel()
{
    int i = blockIdx.x * blockDim.x + threadIdx.x;
    const int BL = B_ * L_;
    if (i < BL) {
        float m = neginf(), s = 0.f;
        #pragma unroll
        for (int t = 0; t < NT_; t++) {
            m = fmaxf(m, g_rmax_p[(size_t)t * BL + i]);
            s += g_rsum_p[(size_t)t * BL + i];
        }
        g_rmax[i] = m;
        g_rsum[i] = s;
    } else if (i < 2 * BL) {   // L_ == S_
        int j = i - BL;
        float m = neginf(), s = 0.f;
        #pragma unroll
        for (int t = 0; t < NT_; t++) {
            m = fmaxf(m, g_cmax_p[(size_t)t * BL + j]);
            s += g_csum_p[(size_t)t * BL + j];
        }
        g_cmax[j] = m;
        g_csum[j] = s;
    }
}

// ---------------- pass 4: conf planes + mask + mconf ----------------
__global__ __launch_bounds__(256) void finalize_kernel(
    const int* __restrict__ ph0, const int* __restrict__ pw0,
    const int* __restrict__ ph1, const int* __restrict__ pw1,
    float* __restrict__ out)
{
    const int NS4 = S_ / 4;
    int t = blockIdx.x * blockDim.x + threadIdx.x;
    if (t >= B_ * L_ * NS4) return;

    int s0  = (t % NS4) * 4;
    int rem = t / NS4;
    int l   = rem % L_;
    int bb  = rem / L_;

    int h0 = __ldg(ph0), w0 = __ldg(pw0), h1 = __ldg(ph1), w1 = __ldg(pw1);
    int i0 = l / w0, j0 = l - i0 * w0;
    bool in0 = (i0 >= 2) && (i0 < h0 - 2) && (j0 >= 2) && (j0 < w0 - 2);

    size_t base = ((size_t)bb * L_ + l) * S_ + s0;
    float4 Ev  = *reinterpret_cast<const float4*>(g_sim + base);
    float rm   = g_rmax[bb * L_ + l];
    float rinv = 1.0f / g_rsum[bb * L_ + l];
    float4 cm4 = *reinterpret_cast<const float4*>(g_cmax + bb * S_ + s0);
    float4 cs4 = *reinterpret_cast<const float4*>(g_csum + bb * S_ + s0);

    float c01v[4], c10v[4], mcv[4];
    const float Es[4]  = {Ev.x, Ev.y, Ev.z, Ev.w};
    const float cms[4] = {cm4.x, cm4.y, cm4.z, cm4.w};
    const float css[4] = {cs4.x, cs4.y, cs4.z, cs4.w};

    #pragma unroll
    for (int e = 0; e < 4; e++) {
        int   s   = s0 + e;
        float E   = Es[e];
        float c01 = E * rinv;
        float c10 = __fdividef(E, css[e]);
        int i1 = s / w1, j1 = s - i1 * w1;
        bool in1 = (i1 >= 2) && (i1 < h1 - 2) && (j1 >= 2) && (j1 < w1 - 2);
        bool mk  = in0 && in1 &&
                   ((c01 > 0.2f && E == rm) || (c10 > 0.2f && E == cms[e]));
        c01v[e] = c01;
        c10v[e] = c10;
        mcv[e]  = mk ? fmaxf(c01, c10) : 0.f;
    }

    const size_t P = (size_t)B_ * L_ * S_;
    *reinterpret_cast<float4*>(out + base)         = make_float4(c01v[0], c01v[1], c01v[2], c01v[3]);
    *reinterpret_cast<float4*>(out + P + base)     = make_float4(c10v[0], c10v[1], c10v[2], c10v[3]);
    *reinterpret_cast<float4*>(out + 2 * P + base) = make_float4(mcv[0],  mcv[1],  mcv[2],  mcv[3]);
}

// ---------------- launch ----------------
extern "C" void kernel_launch(void* const* d_in, const int* in_sizes, int n_in,
                              void* d_out, int out_size)
{
    const float* feat0 = (const float*)d_in[0];
    const float* feat1 = (const float*)d_in[1];
    const float* W     = (const float*)d_in[2];
    const float* bias  = (const float*)d_in[3];
    const int*   h0    = (const int*)d_in[4];
    const int*   w0    = (const int*)d_in[5];
    const int*   h1    = (const int*)d_in[6];
    const int*   w1    = (const int*)d_in[7];
    float* out = (float*)d_out;

    static bool configured = false;
    if (!configured) {
        cudaFuncSetAttribute(sim_kernel,
                             cudaFuncAttributeMaxDynamicSharedMemorySize,
                             2 * STAGE_F * (int)sizeof(float));
        configured = true;
    }

    proj_kernel<<<dim3(2, 75, 1), 256>>>(feat0, W, bias, 0);
    proj_kernel<<<dim3(2, 75, 1), 256>>>(feat1, W, bias, 1);
    sim_kernel<<<dim3(NT_, NT_, B_), 256, 2 * STAGE_F * sizeof(float)>>>();
    reduce_stats_kernel<<<(2 * B_ * L_ + 255) / 256, 256>>>();
    finalize_kernel<<<(B_ * L_ * (S_ / 4) + 255) / 256, 256>>>(h0, w0, h1, w1, out);
}

// round 4
// speedup vs baseline: 1.8584x; 1.1298x over previous
#include <cuda_runtime.h>
#include <cuda_fp16.h>
#include <cstdint>

#define B_ 2
#define L_ 4800
#define S_ 4800
#define C_ 256
#define NT_ 38          // ceil(4800/128)
#define SMPAD 36        // proj kernel smem pad (floats)
#define BL_ (B_ * L_)

// ---- sim kernel smem geometry (fp16) ----
#define HSTRIDE 72                       // halves per smem row (64 data + 8 pad)
#define CHUNKB  (128 * HSTRIDE * 2)      // one operand chunk: 18432 B
#define STAGEB  (2 * CHUNKB)             // A + B chunk: 36864 B
#define DYN_SZ  (2 * STAGEB)             // double buffer: 73728 B

// ---------------- scratch (device globals: no allocs allowed) ----------------
__device__ __half g_f0h[B_ * L_ * C_];
__device__ __half g_f1h[B_ * S_ * C_];
__device__ float  g_sim[(size_t)B_ * L_ * S_];          // stores E = exp(logit)
__device__ float  g_rmax_p[NT_ * BL_];
__device__ float  g_rsum_p[NT_ * BL_];
__device__ float  g_cmax_p[NT_ * B_ * S_];
__device__ float  g_csum_p[NT_ * B_ * S_];
__device__ float  g_rmax[BL_];
__device__ float  g_rsum[BL_];
__device__ float  g_cmax[B_ * S_];
__device__ float  g_csum[B_ * S_];

__device__ __forceinline__ float tf32r(float x) {
    uint32_t u = __float_as_uint(x);
    asm("cvt.rna.tf32.f32 %0, %0;" : "+r"(u));
    return __uint_as_float(u);
}

// tf32 m16n8k8 (proj only)
__device__ __forceinline__ void mma8(float d[4], const uint32_t a[4], const uint32_t b[2]) {
    asm volatile(
        "mma.sync.aligned.m16n8k8.row.col.f32.tf32.tf32.f32 "
        "{%0,%1,%2,%3}, {%4,%5,%6,%7}, {%8,%9}, {%0,%1,%2,%3};"
        : "+f"(d[0]), "+f"(d[1]), "+f"(d[2]), "+f"(d[3])
        : "r"(a[0]), "r"(a[1]), "r"(a[2]), "r"(a[3]), "r"(b[0]), "r"(b[1]));
}

// fp16 m16n8k16 (sim)
__device__ __forceinline__ void mma16(float d[4], uint32_t a0, uint32_t a1,
                                      uint32_t a2, uint32_t a3,
                                      uint32_t b0, uint32_t b1) {
    asm volatile(
        "mma.sync.aligned.m16n8k16.row.col.f32.f16.f16.f32 "
        "{%0,%1,%2,%3}, {%4,%5,%6,%7}, {%8,%9}, {%0,%1,%2,%3};"
        : "+f"(d[0]), "+f"(d[1]), "+f"(d[2]), "+f"(d[3])
        : "r"(a0), "r"(a1), "r"(a2), "r"(a3), "r"(b0), "r"(b1));
}

#define LDSM4(r0, r1, r2, r3, addr)                                            \
    asm volatile("ldmatrix.sync.aligned.m8n8.x4.shared.b16 {%0,%1,%2,%3}, [%4];" \
                 : "=r"(r0), "=r"(r1), "=r"(r2), "=r"(r3) : "r"(addr))

__device__ __forceinline__ float neginf() { return __int_as_float(0xff800000); }

__device__ __forceinline__ uint32_t smaddr(const void* p) {
    return (uint32_t)__cvta_generic_to_shared(p);
}

#define CP16(dst, src, pred)                                                   \
    asm volatile("cp.async.cg.shared.global [%0], [%1], 16, %2;\n" ::          \
                     "r"(dst), "l"(src), "r"((pred) ? 16 : 0))

// ================= proj: f = fp16((X @ W^T + b) / 16) =================
__device__ __forceinline__ void proj_mainloop(
    const float* __restrict__ A, const float* __restrict__ Bm,
    int m0, int n0, float* As, float* Bs, float acc[4][4][4])
{
    const int tid  = threadIdx.x;
    const int lane = tid & 31;
    const int warp = tid >> 5;
    const int wm = warp >> 2, wn = warp & 3;
    const int gp = lane >> 2, tg = lane & 3;

    for (int kc = 0; kc < C_; kc += 32) {
        #pragma unroll
        for (int i = 0; i < 4; i++) {
            int idx = tid + i * 256;
            int r   = idx >> 3;
            int kq  = (idx & 7) * 4;
            float4 va = *reinterpret_cast<const float4*>(A + (size_t)(m0 + r) * C_ + kc + kq);
            va.x = tf32r(va.x); va.y = tf32r(va.y); va.z = tf32r(va.z); va.w = tf32r(va.w);
            *reinterpret_cast<float4*>(As + r * SMPAD + kq) = va;
            float4 vb = *reinterpret_cast<const float4*>(Bm + (size_t)(n0 + r) * C_ + kc + kq);
            vb.x = tf32r(vb.x); vb.y = tf32r(vb.y); vb.z = tf32r(vb.z); vb.w = tf32r(vb.w);
            *reinterpret_cast<float4*>(Bs + r * SMPAD + kq) = vb;
        }
        __syncthreads();
        #pragma unroll
        for (int ks = 0; ks < 4; ks++) {
            const int k0 = ks * 8;
            uint32_t afr[4][4];
            uint32_t bfr[4][2];
            #pragma unroll
            for (int mf = 0; mf < 4; mf++) {
                const float* p = As + (wm * 64 + mf * 16 + gp) * SMPAD + k0 + tg;
                afr[mf][0] = __float_as_uint(p[0]);
                afr[mf][1] = __float_as_uint(p[8 * SMPAD]);
                afr[mf][2] = __float_as_uint(p[4]);
                afr[mf][3] = __float_as_uint(p[8 * SMPAD + 4]);
            }
            #pragma unroll
            for (int nf = 0; nf < 4; nf++) {
                const float* p = Bs + (wn * 32 + nf * 8 + gp) * SMPAD + k0 + tg;
                bfr[nf][0] = __float_as_uint(p[0]);
                bfr[nf][1] = __float_as_uint(p[4]);
            }
            #pragma unroll
            for (int mf = 0; mf < 4; mf++)
                #pragma unroll
                for (int nf = 0; nf < 4; nf++)
                    mma8(acc[mf][nf], afr[mf], bfr[nf]);
        }
        __syncthreads();
    }
}

__global__ __launch_bounds__(256) void proj_kernel(
    const float* __restrict__ X, const float* __restrict__ W,
    const float* __restrict__ bias, int which)
{
    __shared__ float As[128 * SMPAD];
    __shared__ float Bs[128 * SMPAD];
    float acc[4][4][4] = {};

    const int n0 = blockIdx.x * 128;
    const int m0 = blockIdx.y * 128;
    proj_mainloop(X, W, m0, n0, As, Bs, acc);

    __half* O = which ? g_f1h : g_f0h;
    const int tid = threadIdx.x, lane = tid & 31, warp = tid >> 5;
    const int wm = warp >> 2, wn = warp & 3, gp = lane >> 2, tg = lane & 3;

    #pragma unroll
    for (int mf = 0; mf < 4; mf++) {
        int row = m0 + wm * 64 + mf * 16 + gp;
        #pragma unroll
        for (int nf = 0; nf < 4; nf++) {
            int col = n0 + wn * 32 + nf * 8 + 2 * tg;
            float b0 = __ldg(bias + col), b1 = __ldg(bias + col + 1);
            #pragma unroll
            for (int h = 0; h < 2; h++) {
                __half2 v = __floats2half2_rn(
                    (acc[mf][nf][2 * h]     + b0) * 0.0625f,
                    (acc[mf][nf][2 * h + 1] + b1) * 0.0625f);
                *reinterpret_cast<__half2*>(O + (size_t)(row + 8 * h) * C_ + col) = v;
            }
        }
    }
}

// ======== sim (fp16 mma + ldmatrix): E = exp(logit) + row/col (max,sum) ========
__global__ __launch_bounds__(256, 2) void sim_kernel()
{
    extern __shared__ char dynp[];
    __shared__ float red_m[4 * 128];
    __shared__ float red_s[4 * 128];
    __shared__ float redc_m[2 * 128];
    __shared__ float redc_s[2 * 128];

    const int tn = blockIdx.x, tm = blockIdx.y, bb = blockIdx.z;
    const int n0 = tn * 128, m0 = tm * 128;
    const __half* A  = g_f0h + (size_t)bb * L_ * C_;
    const __half* Bm = g_f1h + (size_t)bb * S_ * C_;

    const int tid  = threadIdx.x;
    const int lane = tid & 31;
    const int warp = tid >> 5;
    const int wm = warp >> 2, wn = warp & 3;
    const int gp = lane >> 2, tg = lane & 3;

    float acc[4][4][4] = {};

    // ---- cp.async loader: chunk = 128 rows x 64 halves per operand ----
    const int cr = tid >> 1;            // row 0..127 (2 threads per row)
    const int cs = (tid & 1) * 4;       // segment base (8 x 16B segments per row)
    auto load_chunk = [&](int c, int buf) {
        __half* Ab = (__half*)(dynp + buf * STAGEB);
        __half* Bb = (__half*)(dynp + buf * STAGEB + CHUNKB);
        const int kc = c * 64;
        int gr = m0 + cr; bool oa = gr < L_;
        int gn = n0 + cr; bool ob = gn < S_;
        const __half* arow = A + (size_t)(oa ? gr : 0) * C_ + kc;
        const __half* brow = Bm + (size_t)(ob ? gn : 0) * C_ + kc;
        #pragma unroll
        for (int q = 0; q < 4; q++) {
            int kk = (cs + q) * 8;      // halves
            CP16(smaddr(Ab + cr * HSTRIDE + kk), arow + kk, oa);
            CP16(smaddr(Bb + cr * HSTRIDE + kk), brow + kk, ob);
        }
    };

    // ldmatrix per-lane address components (in bytes, relative to operand base)
    const uint32_t aoff = (uint32_t)((wm * 64 + (lane & 15)) * HSTRIDE + (lane >> 4) * 8) * 2;
    const uint32_t boff = (uint32_t)((wn * 32 + (lane & 7) + ((lane >> 4) & 1) * 8) * HSTRIDE
                                     + ((lane >> 3) & 1) * 8) * 2;

    load_chunk(0, 0);
    asm volatile("cp.async.commit_group;\n");

    #pragma unroll
    for (int c = 0; c < 4; c++) {
        if (c < 3) {
            load_chunk(c + 1, (c + 1) & 1);
            asm volatile("cp.async.commit_group;\n");
            asm volatile("cp.async.wait_group 1;\n");
        } else {
            asm volatile("cp.async.wait_group 0;\n");
        }
        __syncthreads();

        const uint32_t Abase = smaddr(dynp + (c & 1) * STAGEB) + aoff;
        const uint32_t Bbase = smaddr(dynp + (c & 1) * STAGEB + CHUNKB) + boff;

        #pragma unroll
        for (int ks = 0; ks < 4; ks++) {
            const uint32_t kb = (uint32_t)(ks * 16 * 2);   // bytes
            uint32_t af[4][4];
            uint32_t bf[4][2];
            #pragma unroll
            for (int mf = 0; mf < 4; mf++)
                LDSM4(af[mf][0], af[mf][1], af[mf][2], af[mf][3],
                      Abase + (uint32_t)(mf * 16 * HSTRIDE * 2) + kb);
            #pragma unroll
            for (int p = 0; p < 2; p++)
                LDSM4(bf[2 * p][0], bf[2 * p][1], bf[2 * p + 1][0], bf[2 * p + 1][1],
                      Bbase + (uint32_t)(p * 16 * HSTRIDE * 2) + kb);
            #pragma unroll
            for (int mf = 0; mf < 4; mf++)
                #pragma unroll
                for (int nf = 0; nf < 4; nf++)
                    mma16(acc[mf][nf], af[mf][0], af[mf][1], af[mf][2], af[mf][3],
                          bf[nf][0], bf[nf][1]);
        }
        __syncthreads();
    }

    // ---- transform in place: acc := E = exp(logit) ----
    #pragma unroll
    for (int mf = 0; mf < 4; mf++)
        #pragma unroll
        for (int nf = 0; nf < 4; nf++)
            #pragma unroll
            for (int e = 0; e < 4; e++)
                acc[mf][nf][e] = __expf(acc[mf][nf][e] * 10.0f);

    // ---- store E ----
    #pragma unroll
    for (int mf = 0; mf < 4; mf++)
        #pragma unroll
        for (int h = 0; h < 2; h++) {
            int row = m0 + wm * 64 + mf * 16 + 8 * h + gp;
            if (row < L_) {
                #pragma unroll
                for (int nf = 0; nf < 4; nf++) {
                    int s = n0 + wn * 32 + nf * 8 + 2 * tg;
                    if (s < S_) {
                        float2 v = make_float2(acc[mf][nf][2 * h], acc[mf][nf][2 * h + 1]);
                        *reinterpret_cast<float2*>(&g_sim[((size_t)bb * L_ + row) * S_ + s]) = v;
                    }
                }
            }
        }

    // ---- row partials over this tile's 128 cols ----
    #pragma unroll
    for (int mf = 0; mf < 4; mf++)
        #pragma unroll
        for (int h = 0; h < 2; h++) {
            float m = neginf(), smm = 0.f;
            #pragma unroll
            for (int nf = 0; nf < 4; nf++)
                #pragma unroll
                for (int ch = 0; ch < 2; ch++) {
                    int s = n0 + wn * 32 + nf * 8 + 2 * tg + ch;
                    if (s < S_) {
                        float v = acc[mf][nf][2 * h + ch];
                        m = fmaxf(m, v);
                        smm += v;
                    }
                }
            m   = fmaxf(m, __shfl_xor_sync(0xffffffffu, m, 1));
            m   = fmaxf(m, __shfl_xor_sync(0xffffffffu, m, 2));
            smm += __shfl_xor_sync(0xffffffffu, smm, 1);
            smm += __shfl_xor_sync(0xffffffffu, smm, 2);
            if (tg == 0) {
                int rib = wm * 64 + mf * 16 + 8 * h + gp;
                red_m[wn * 128 + rib] = m;
                red_s[wn * 128 + rib] = smm;
            }
        }
    __syncthreads();

    // ---- col partials over this tile's 128 rows ----
    #pragma unroll
    for (int nf = 0; nf < 4; nf++)
        #pragma unroll
        for (int ch = 0; ch < 2; ch++) {
            float m = neginf(), smm = 0.f;
            #pragma unroll
            for (int mf = 0; mf < 4; mf++)
                #pragma unroll
                for (int h = 0; h < 2; h++) {
                    int row = m0 + wm * 64 + mf * 16 + 8 * h + gp;
                    if (row < L_) {
                        float v = acc[mf][nf][2 * h + ch];
                        m = fmaxf(m, v);
                        smm += v;
                    }
                }
            m   = fmaxf(m, __shfl_xor_sync(0xffffffffu, m, 4));
            m   = fmaxf(m, __shfl_xor_sync(0xffffffffu, m, 8));
            m   = fmaxf(m, __shfl_xor_sync(0xffffffffu, m, 16));
            smm += __shfl_xor_sync(0xffffffffu, smm, 4);
            smm += __shfl_xor_sync(0xffffffffu, smm, 8);
            smm += __shfl_xor_sync(0xffffffffu, smm, 16);
            if (gp == 0) {
                int cib = wn * 32 + nf * 8 + 2 * tg + ch;
                redc_m[wm * 128 + cib] = m;
                redc_s[wm * 128 + cib] = smm;
            }
        }

    // merge the 4 n-warp row partials; write transposed [tile][row]
    if (tid < 128) {
        float m = red_m[tid], smm = red_s[tid];
        #pragma unroll
        for (int j = 1; j < 4; j++) {
            m   = fmaxf(m, red_m[j * 128 + tid]);
            smm += red_s[j * 128 + tid];
        }
        int gl = m0 + tid;
        if (gl < L_) {
            size_t o = (size_t)tn * BL_ + bb * L_ + gl;
            g_rmax_p[o] = m;
            g_rsum_p[o] = smm;
        }
    }
    __syncthreads();

    // merge the 2 m-warp col partials; write transposed [tile][col]
    if (tid < 128) {
        float m   = fmaxf(redc_m[tid], redc_m[128 + tid]);
        float smm = redc_s[tid] + redc_s[128 + tid];
        int gs = n0 + tid;
        if (gs < S_) {
            size_t o = (size_t)tm * (B_ * S_) + bb * S_ + gs;
            g_cmax_p[o] = m;
            g_csum_p[o] = smm;
        }
    }
}

// ---------------- pass 3: reduce tile partials (coalesced) ----------------
__global__ __launch_bounds__(256) void reduce_stats_kernel()
{
    int i = blockIdx.x * blockDim.x + threadIdx.x;
    if (i < BL_) {
        float m = neginf(), s = 0.f;
        #pragma unroll
        for (int t = 0; t < NT_; t++) {
            m = fmaxf(m, g_rmax_p[(size_t)t * BL_ + i]);
            s += g_rsum_p[(size_t)t * BL_ + i];
        }
        g_rmax[i] = m;
        g_rsum[i] = s;
    } else if (i < 2 * BL_) {
        int j = i - BL_;
        float m = neginf(), s = 0.f;
        #pragma unroll
        for (int t = 0; t < NT_; t++) {
            m = fmaxf(m, g_cmax_p[(size_t)t * BL_ + j]);
            s += g_csum_p[(size_t)t * BL_ + j];
        }
        g_cmax[j] = m;
        g_csum[j] = s;
    }
}

// ---------------- pass 4: conf planes + mask + mconf ----------------
__global__ __launch_bounds__(256) void finalize_kernel(
    const int* __restrict__ ph0, const int* __restrict__ pw0,
    const int* __restrict__ ph1, const int* __restrict__ pw1,
    float* __restrict__ out)
{
    const int NS4 = S_ / 4;
    int t = blockIdx.x * blockDim.x + threadIdx.x;
    if (t >= B_ * L_ * NS4) return;

    int s0  = (t % NS4) * 4;
    int rem = t / NS4;
    int l   = rem % L_;
    int bb  = rem / L_;

    int h0 = __ldg(ph0), w0 = __ldg(pw0), h1 = __ldg(ph1), w1 = __ldg(pw1);
    int i0 = l / w0, j0 = l - i0 * w0;
    bool in0 = (i0 >= 2) && (i0 < h0 - 2) && (j0 >= 2) && (j0 < w0 - 2);

    size_t base = ((size_t)bb * L_ + l) * S_ + s0;
    float4 Ev  = *reinterpret_cast<const float4*>(g_sim + base);
    float rm   = g_rmax[bb * L_ + l];
    float rinv = 1.0f / g_rsum[bb * L_ + l];
    float4 cm4 = *reinterpret_cast<const float4*>(g_cmax + bb * S_ + s0);
    float4 cs4 = *reinterpret_cast<const float4*>(g_csum + bb * S_ + s0);

    float c01v[4], c10v[4], mcv[4];
    const float Es4[4] = {Ev.x, Ev.y, Ev.z, Ev.w};
    const float cms[4] = {cm4.x, cm4.y, cm4.z, cm4.w};
    const float css[4] = {cs4.x, cs4.y, cs4.z, cs4.w};

    #pragma unroll
    for (int e = 0; e < 4; e++) {
        int   s   = s0 + e;
        float E   = Es4[e];
        float c01 = E * rinv;
        float c10 = __fdividef(E, css[e]);
        int i1 = s / w1, j1 = s - i1 * w1;
        bool in1 = (i1 >= 2) && (i1 < h1 - 2) && (j1 >= 2) && (j1 < w1 - 2);
        bool mk  = in0 && in1 &&
                   ((c01 > 0.2f && E == rm) || (c10 > 0.2f && E == cms[e]));
        c01v[e] = c01;
        c10v[e] = c10;
        mcv[e]  = mk ? fmaxf(c01, c10) : 0.f;
    }

    const size_t P = (size_t)B_ * L_ * S_;
    *reinterpret_cast<float4*>(out + base)         = make_float4(c01v[0], c01v[1], c01v[2], c01v[3]);
    *reinterpret_cast<float4*>(out + P + base)     = make_float4(c10v[0], c10v[1], c10v[2], c10v[3]);
    *reinterpret_cast<float4*>(out + 2 * P + base) = make_float4(mcv[0],  mcv[1],  mcv[2],  mcv[3]);
}

// ---------------- launch ----------------
extern "C" void kernel_launch(void* const* d_in, const int* in_sizes, int n_in,
                              void* d_out, int out_size)
{
    const float* feat0 = (const float*)d_in[0];
    const float* feat1 = (const float*)d_in[1];
    const float* W     = (const float*)d_in[2];
    const float* bias  = (const float*)d_in[3];
    const int*   h0    = (const int*)d_in[4];
    const int*   w0    = (const int*)d_in[5];
    const int*   h1    = (const int*)d_in[6];
    const int*   w1    = (const int*)d_in[7];
    float* out = (float*)d_out;

    static bool configured = false;
    if (!configured) {
        cudaFuncSetAttribute(sim_kernel,
                             cudaFuncAttributeMaxDynamicSharedMemorySize, DYN_SZ);
        configured = true;
    }

    proj_kernel<<<dim3(2, 75, 1), 256>>>(feat0, W, bias, 0);
    proj_kernel<<<dim3(2, 75, 1), 256>>>(feat1, W, bias, 1);
    sim_kernel<<<dim3(NT_, NT_, B_), 256, DYN_SZ>>>();
    reduce_stats_kernel<<<(2 * BL_ + 255) / 256, 256>>>();
    finalize_kernel<<<(B_ * L_ * (S_ / 4) + 255) / 256, 256>>>(h0, w0, h1, w1, out);
}

// round 5
// speedup vs baseline: 1.9408x; 1.0444x over previous
#include <cuda_runtime.h>
#include <cuda_fp16.h>
#include <cstdint>

#define B_ 2
#define L_ 4800
#define S_ 4800
#define C_ 256
#define NT_ 38          // ceil(4800/128)
#define NSPLIT 4        // n-range splits per m-tile
#define SMPAD 36        // proj kernel smem pad (floats)
#define BL_ (B_ * L_)

// ---- sim kernel smem geometry (fp16) ----
#define ASTRIDE 264                      // halves per A smem row (256 data + 8 pad) -> 528B
#define HSTRIDE 72                       // halves per B smem row (64 data + 8 pad)  -> 144B
#define ABYTES  (128 * ASTRIDE * 2)      // resident A tile: 67584 B
#define BCHUNKB (128 * HSTRIDE * 2)      // one B chunk: 18432 B
#define DYN_SZ  (ABYTES + 2 * BCHUNKB)   // 104448 B

// ---------------- scratch (device globals: no allocs allowed) ----------------
__device__ __half g_f0h[B_ * L_ * C_];
__device__ __half g_f1h[B_ * S_ * C_];
__device__ float  g_sim[(size_t)B_ * L_ * S_];          // stores E = exp(logit)
__device__ float  g_rmax_p[NSPLIT * BL_];
__device__ float  g_rsum_p[NSPLIT * BL_];
__device__ float  g_cmax_p[NT_ * B_ * S_];
__device__ float  g_csum_p[NT_ * B_ * S_];
__device__ float  g_rmax[BL_];
__device__ float  g_rsum[BL_];
__device__ float  g_cmax[B_ * S_];
__device__ float  g_csum[B_ * S_];

__device__ __forceinline__ float tf32r(float x) {
    uint32_t u = __float_as_uint(x);
    asm("cvt.rna.tf32.f32 %0, %0;" : "+r"(u));
    return __uint_as_float(u);
}

// tf32 m16n8k8 (proj only)
__device__ __forceinline__ void mma8(float d[4], const uint32_t a[4], const uint32_t b[2]) {
    asm volatile(
        "mma.sync.aligned.m16n8k8.row.col.f32.tf32.tf32.f32 "
        "{%0,%1,%2,%3}, {%4,%5,%6,%7}, {%8,%9}, {%0,%1,%2,%3};"
        : "+f"(d[0]), "+f"(d[1]), "+f"(d[2]), "+f"(d[3])
        : "r"(a[0]), "r"(a[1]), "r"(a[2]), "r"(a[3]), "r"(b[0]), "r"(b[1]));
}

// fp16 m16n8k16 (sim)
__device__ __forceinline__ void mma16(float d[4], uint32_t a0, uint32_t a1,
                                      uint32_t a2, uint32_t a3,
                                      uint32_t b0, uint32_t b1) {
    asm volatile(
        "mma.sync.aligned.m16n8k16.row.col.f32.f16.f16.f32 "
        "{%0,%1,%2,%3}, {%4,%5,%6,%7}, {%8,%9}, {%0,%1,%2,%3};"
        : "+f"(d[0]), "+f"(d[1]), "+f"(d[2]), "+f"(d[3])
        : "r"(a0), "r"(a1), "r"(a2), "r"(a3), "r"(b0), "r"(b1));
}

#define LDSM4(r0, r1, r2, r3, addr)                                            \
    asm volatile("ldmatrix.sync.aligned.m8n8.x4.shared.b16 {%0,%1,%2,%3}, [%4];" \
                 : "=r"(r0), "=r"(r1), "=r"(r2), "=r"(r3) : "r"(addr))

__device__ __forceinline__ float neginf() { return __int_as_float(0xff800000); }

__device__ __forceinline__ uint32_t smaddr(const void* p) {
    return (uint32_t)__cvta_generic_to_shared(p);
}

#define CP16(dst, src, pred)                                                   \
    asm volatile("cp.async.cg.shared.global [%0], [%1], 16, %2;\n" ::          \
                     "r"(dst), "l"(src), "r"((pred) ? 16 : 0))

// ================= proj: f = fp16((X @ W^T + b) / 16) =================
__device__ __forceinline__ void proj_mainloop(
    const float* __restrict__ A, const float* __restrict__ Bm,
    int m0, int n0, float* As, float* Bs, float acc[4][4][4])
{
    const int tid  = threadIdx.x;
    const int lane = tid & 31;
    const int warp = tid >> 5;
    const int wm = warp >> 2, wn = warp & 3;
    const int gp = lane >> 2, tg = lane & 3;

    for (int kc = 0; kc < C_; kc += 32) {
        #pragma unroll
        for (int i = 0; i < 4; i++) {
            int idx = tid + i * 256;
            int r   = idx >> 3;
            int kq  = (idx & 7) * 4;
            float4 va = *reinterpret_cast<const float4*>(A + (size_t)(m0 + r) * C_ + kc + kq);
            va.x = tf32r(va.x); va.y = tf32r(va.y); va.z = tf32r(va.z); va.w = tf32r(va.w);
            *reinterpret_cast<float4*>(As + r * SMPAD + kq) = va;
            float4 vb = *reinterpret_cast<const float4*>(Bm + (size_t)(n0 + r) * C_ + kc + kq);
            vb.x = tf32r(vb.x); vb.y = tf32r(vb.y); vb.z = tf32r(vb.z); vb.w = tf32r(vb.w);
            *reinterpret_cast<float4*>(Bs + r * SMPAD + kq) = vb;
        }
        __syncthreads();
        #pragma unroll
        for (int ks = 0; ks < 4; ks++) {
            const int k0 = ks * 8;
            uint32_t afr[4][4];
            uint32_t bfr[4][2];
            #pragma unroll
            for (int mf = 0; mf < 4; mf++) {
                const float* p = As + (wm * 64 + mf * 16 + gp) * SMPAD + k0 + tg;
                afr[mf][0] = __float_as_uint(p[0]);
                afr[mf][1] = __float_as_uint(p[8 * SMPAD]);
                afr[mf][2] = __float_as_uint(p[4]);
                afr[mf][3] = __float_as_uint(p[8 * SMPAD + 4]);
            }
            #pragma unroll
            for (int nf = 0; nf < 4; nf++) {
                const float* p = Bs + (wn * 32 + nf * 8 + gp) * SMPAD + k0 + tg;
                bfr[nf][0] = __float_as_uint(p[0]);
                bfr[nf][1] = __float_as_uint(p[4]);
            }
            #pragma unroll
            for (int mf = 0; mf < 4; mf++)
                #pragma unroll
                for (int nf = 0; nf < 4; nf++)
                    mma8(acc[mf][nf], afr[mf], bfr[nf]);
        }
        __syncthreads();
    }
}

__global__ __launch_bounds__(256) void proj_kernel(
    const float* __restrict__ X, const float* __restrict__ W,
    const float* __restrict__ bias, int which)
{
    __shared__ float As[128 * SMPAD];
    __shared__ float Bs[128 * SMPAD];
    float acc[4][4][4] = {};

    const int n0 = blockIdx.x * 128;
    const int m0 = blockIdx.y * 128;
    proj_mainloop(X, W, m0, n0, As, Bs, acc);

    __half* O = which ? g_f1h : g_f0h;
    const int tid = threadIdx.x, lane = tid & 31, warp = tid >> 5;
    const int wm = warp >> 2, wn = warp & 3, gp = lane >> 2, tg = lane & 3;

    #pragma unroll
    for (int mf = 0; mf < 4; mf++) {
        int row = m0 + wm * 64 + mf * 16 + gp;
        #pragma unroll
        for (int nf = 0; nf < 4; nf++) {
            int col = n0 + wn * 32 + nf * 8 + 2 * tg;
            float b0 = __ldg(bias + col), b1 = __ldg(bias + col + 1);
            #pragma unroll
            for (int h = 0; h < 2; h++) {
                __half2 v = __floats2half2_rn(
                    (acc[mf][nf][2 * h]     + b0) * 0.0625f,
                    (acc[mf][nf][2 * h + 1] + b1) * 0.0625f);
                *reinterpret_cast<__half2*>(O + (size_t)(row + 8 * h) * C_ + col) = v;
            }
        }
    }
}

// ======== sim (persistent-A): E = exp(logit) + row/col (max,sum) ========
__global__ __launch_bounds__(256, 2) void sim_kernel()
{
    extern __shared__ char dynp[];          // [A tile | B buf0 | B buf1]
    __shared__ float red_m[4 * 128];
    __shared__ float red_s[4 * 128];
    __shared__ float redc_m[2 * 128];
    __shared__ float redc_s[2 * 128];

    const int sidx = blockIdx.x;            // n-range split
    const int tm   = blockIdx.y;
    const int bb   = blockIdx.z;
    const int m0   = tm * 128;
    const __half* A  = g_f0h + (size_t)bb * L_ * C_;
    const __half* Bm = g_f1h + (size_t)bb * S_ * C_;

    const int tid  = threadIdx.x;
    const int lane = tid & 31;
    const int warp = tid >> 5;
    const int wm = warp >> 2, wn = warp & 3;
    const int gp = lane >> 2, tg = lane & 3;

    __half* Asm = (__half*)dynp;
    char*   Bbuf0 = dynp + ABYTES;

    // ---- resident A tile load: 128 rows x 256 halves, stride ASTRIDE ----
    {
        const int r    = tid >> 1;
        const int half = tid & 1;
        int gr = m0 + r; bool oa = gr < L_;
        const __half* arow = A + (size_t)(oa ? gr : 0) * C_;
        #pragma unroll
        for (int i = 0; i < 16; i++) {
            int seg = half * 16 + i;        // 16B segment index (0..31)
            CP16(smaddr(Asm + r * ASTRIDE + seg * 8), arow + seg * 8, oa);
        }
    }

    // ---- B chunk loader: 128 rows x 64 halves into buf ----
    const int br = tid >> 1;
    const int bq0 = (tid & 1) * 4;
    auto load_bchunk = [&](int tn, int c, int buf) {
        __half* Bb = (__half*)(Bbuf0 + buf * BCHUNKB);
        const int kc = c * 64;
        int gn = tn * 128 + br; bool ob = gn < S_;
        const __half* brow = Bm + (size_t)(ob ? gn : 0) * C_ + kc;
        #pragma unroll
        for (int q = 0; q < 4; q++) {
            int kk = (bq0 + q) * 8;
            CP16(smaddr(Bb + br * HSTRIDE + kk), brow + kk, ob);
        }
    };

    // ldmatrix per-lane offsets (bytes)
    const uint32_t aoff = (uint32_t)((wm * 64 + (lane & 15)) * ASTRIDE + (lane >> 4) * 8) * 2;
    const uint32_t boff = (uint32_t)((wn * 32 + (lane & 7) + ((lane >> 4) & 1) * 8) * HSTRIDE
                                     + ((lane >> 3) & 1) * 8) * 2;
    const uint32_t Abase = smaddr(Asm) + aoff;

    // n-tile list for this CTA
    int tnlist[10];
    int ntn = 0;
    for (int tn = sidx; tn < NT_; tn += NSPLIT) tnlist[ntn++] = tn;

    // prologue: A + first B chunk in group 0
    load_bchunk(tnlist[0], 0, 0);
    asm volatile("cp.async.commit_group;\n");

    // register-resident row stats across all n-tiles
    float rmx[8], rsm[8];
    #pragma unroll
    for (int i = 0; i < 8; i++) { rmx[i] = neginf(); rsm[i] = 0.f; }

    const int ntot = ntn * 4;               // total chunks
    int g = 0;                              // flat chunk index

    for (int ti = 0; ti < ntn; ti++) {
        const int tn = tnlist[ti];
        const int n0 = tn * 128;
        float acc[4][4][4] = {};

        #pragma unroll
        for (int c = 0; c < 4; c++) {
            // load next chunk (possibly next tile's chunk 0)
            if (g + 1 < ntot) {
                int gn1 = g + 1;
                load_bchunk(tnlist[gn1 >> 2], gn1 & 3, gn1 & 1);
                asm volatile("cp.async.commit_group;\n");
                asm volatile("cp.async.wait_group 1;\n");
            } else {
                asm volatile("cp.async.wait_group 0;\n");
            }
            __syncthreads();

            const uint32_t Bbase = smaddr(Bbuf0 + (g & 1) * BCHUNKB) + boff;
            const uint32_t Ac = Abase + (uint32_t)(c * 64 * 2);   // chunk K offset in A

            #pragma unroll
            for (int ks = 0; ks < 4; ks++) {
                const uint32_t kb = (uint32_t)(ks * 16 * 2);
                uint32_t af[4][4];
                uint32_t bf[4][2];
                #pragma unroll
                for (int mf = 0; mf < 4; mf++)
                    LDSM4(af[mf][0], af[mf][1], af[mf][2], af[mf][3],
                          Ac + (uint32_t)(mf * 16 * ASTRIDE * 2) + kb);
                #pragma unroll
                for (int p = 0; p < 2; p++)
                    LDSM4(bf[2 * p][0], bf[2 * p][1], bf[2 * p + 1][0], bf[2 * p + 1][1],
                          Bbase + (uint32_t)(p * 16 * HSTRIDE * 2) + kb);
                #pragma unroll
                for (int mf = 0; mf < 4; mf++)
                    #pragma unroll
                    for (int nf = 0; nf < 4; nf++)
                        mma16(acc[mf][nf], af[mf][0], af[mf][1], af[mf][2], af[mf][3],
                              bf[nf][0], bf[nf][1]);
            }
            __syncthreads();
            g++;
        }

        // ---- epilogue for this n-tile ----
        // acc := E = exp(logit)
        #pragma unroll
        for (int mf = 0; mf < 4; mf++)
            #pragma unroll
            for (int nf = 0; nf < 4; nf++)
                #pragma unroll
                for (int e = 0; e < 4; e++)
                    acc[mf][nf][e] = __expf(acc[mf][nf][e] * 10.0f);

        // store E
        #pragma unroll
        for (int mf = 0; mf < 4; mf++)
            #pragma unroll
            for (int h = 0; h < 2; h++) {
                int row = m0 + wm * 64 + mf * 16 + 8 * h + gp;
                if (row < L_) {
                    #pragma unroll
                    for (int nf = 0; nf < 4; nf++) {
                        int s = n0 + wn * 32 + nf * 8 + 2 * tg;
                        if (s < S_) {
                            float2 v = make_float2(acc[mf][nf][2 * h], acc[mf][nf][2 * h + 1]);
                            *reinterpret_cast<float2*>(&g_sim[((size_t)bb * L_ + row) * S_ + s]) = v;
                        }
                    }
                }
            }

        // accumulate row stats in registers (cols of this tile)
        #pragma unroll
        for (int mf = 0; mf < 4; mf++)
            #pragma unroll
            for (int h = 0; h < 2; h++) {
                float m = rmx[mf * 2 + h], smm = rsm[mf * 2 + h];
                #pragma unroll
                for (int nf = 0; nf < 4; nf++)
                    #pragma unroll
                    for (int ch = 0; ch < 2; ch++) {
                        int s = n0 + wn * 32 + nf * 8 + 2 * tg + ch;
                        if (s < S_) {
                            float v = acc[mf][nf][2 * h + ch];
                            m = fmaxf(m, v);
                            smm += v;
                        }
                    }
                rmx[mf * 2 + h] = m;
                rsm[mf * 2 + h] = smm;
            }

        // col partials over this tile's 128 rows
        #pragma unroll
        for (int nf = 0; nf < 4; nf++)
            #pragma unroll
            for (int ch = 0; ch < 2; ch++) {
                float m = neginf(), smm = 0.f;
                #pragma unroll
                for (int mf = 0; mf < 4; mf++)
                    #pragma unroll
                    for (int h = 0; h < 2; h++) {
                        int row = m0 + wm * 64 + mf * 16 + 8 * h + gp;
                        if (row < L_) {
                            float v = acc[mf][nf][2 * h + ch];
                            m = fmaxf(m, v);
                            smm += v;
                        }
                    }
                m   = fmaxf(m, __shfl_xor_sync(0xffffffffu, m, 4));
                m   = fmaxf(m, __shfl_xor_sync(0xffffffffu, m, 8));
                m   = fmaxf(m, __shfl_xor_sync(0xffffffffu, m, 16));
                smm += __shfl_xor_sync(0xffffffffu, smm, 4);
                smm += __shfl_xor_sync(0xffffffffu, smm, 8);
                smm += __shfl_xor_sync(0xffffffffu, smm, 16);
                if (gp == 0) {
                    int cib = wn * 32 + nf * 8 + 2 * tg + ch;
                    redc_m[wm * 128 + cib] = m;
                    redc_s[wm * 128 + cib] = smm;
                }
            }
        __syncthreads();
        if (tid < 128) {
            float m   = fmaxf(redc_m[tid], redc_m[128 + tid]);
            float smm = redc_s[tid] + redc_s[128 + tid];
            int gs = n0 + tid;
            if (gs < S_) {
                size_t o = (size_t)tm * (B_ * S_) + bb * S_ + gs;
                g_cmax_p[o] = m;
                g_csum_p[o] = smm;
            }
        }
        __syncthreads();
    }

    // ---- final row-partial write (one per CTA) ----
    #pragma unroll
    for (int i = 0; i < 8; i++) {
        float m = rmx[i], smm = rsm[i];
        m   = fmaxf(m, __shfl_xor_sync(0xffffffffu, m, 1));
        m   = fmaxf(m, __shfl_xor_sync(0xffffffffu, m, 2));
        smm += __shfl_xor_sync(0xffffffffu, smm, 1);
        smm += __shfl_xor_sync(0xffffffffu, smm, 2);
        if (tg == 0) {
            int rib = wm * 64 + (i >> 1) * 16 + (i & 1) * 8 + gp;
            red_m[wn * 128 + rib] = m;
            red_s[wn * 128 + rib] = smm;
        }
    }
    __syncthreads();
    if (tid < 128) {
        float m = red_m[tid], smm = red_s[tid];
        #pragma unroll
        for (int j = 1; j < 4; j++) {
            m   = fmaxf(m, red_m[j * 128 + tid]);
            smm += red_s[j * 128 + tid];
        }
        int gl = m0 + tid;
        if (gl < L_) {
            size_t o = (size_t)sidx * BL_ + bb * L_ + gl;
            g_rmax_p[o] = m;
            g_rsum_p[o] = smm;
        }
    }
}

// ---------------- pass 3: reduce tile partials (coalesced) ----------------
__global__ __launch_bounds__(256) void reduce_stats_kernel()
{
    int i = blockIdx.x * blockDim.x + threadIdx.x;
    if (i < BL_) {
        float m = neginf(), s = 0.f;
        #pragma unroll
        for (int t = 0; t < NSPLIT; t++) {
            m = fmaxf(m, g_rmax_p[(size_t)t * BL_ + i]);
            s += g_rsum_p[(size_t)t * BL_ + i];
        }
        g_rmax[i] = m;
        g_rsum[i] = s;
    } else if (i < 2 * BL_) {
        int j = i - BL_;
        float m = neginf(), s = 0.f;
        #pragma unroll
        for (int t = 0; t < NT_; t++) {
            m = fmaxf(m, g_cmax_p[(size_t)t * BL_ + j]);
            s += g_csum_p[(size_t)t * BL_ + j];
        }
        g_cmax[j] = m;
        g_csum[j] = s;
    }
}

// ---------------- pass 4: conf planes + mask + mconf ----------------
__global__ __launch_bounds__(256) void finalize_kernel(
    const int* __restrict__ ph0, const int* __restrict__ pw0,
    const int* __restrict__ ph1, const int* __restrict__ pw1,
    float* __restrict__ out)
{
    const int NS4 = S_ / 4;
    int t = blockIdx.x * blockDim.x + threadIdx.x;
    if (t >= B_ * L_ * NS4) return;

    int s0  = (t % NS4) * 4;
    int rem = t / NS4;
    int l   = rem % L_;
    int bb  = rem / L_;

    int h0 = __ldg(ph0), w0 = __ldg(pw0), h1 = __ldg(ph1), w1 = __ldg(pw1);
    int i0 = l / w0, j0 = l - i0 * w0;
    bool in0 = (i0 >= 2) && (i0 < h0 - 2) && (j0 >= 2) && (j0 < w0 - 2);

    size_t base = ((size_t)bb * L_ + l) * S_ + s0;
    float4 Ev  = *reinterpret_cast<const float4*>(g_sim + base);
    float rm   = g_rmax[bb * L_ + l];
    float rinv = 1.0f / g_rsum[bb * L_ + l];
    float4 cm4 = *reinterpret_cast<const float4*>(g_cmax + bb * S_ + s0);
    float4 cs4 = *reinterpret_cast<const float4*>(g_csum + bb * S_ + s0);

    float c01v[4], c10v[4], mcv[4];
    const float Es4[4] = {Ev.x, Ev.y, Ev.z, Ev.w};
    const float cms[4] = {cm4.x, cm4.y, cm4.z, cm4.w};
    const float css[4] = {cs4.x, cs4.y, cs4.z, cs4.w};

    #pragma unroll
    for (int e = 0; e < 4; e++) {
        int   s   = s0 + e;
        float E   = Es4[e];
        float c01 = E * rinv;
        float c10 = __fdividef(E, css[e]);
        int i1 = s / w1, j1 = s - i1 * w1;
        bool in1 = (i1 >= 2) && (i1 < h1 - 2) && (j1 >= 2) && (j1 < w1 - 2);
        bool mk  = in0 && in1 &&
                   ((c01 > 0.2f && E == rm) || (c10 > 0.2f && E == cms[e]));
        c01v[e] = c01;
        c10v[e] = c10;
        mcv[e]  = mk ? fmaxf(c01, c10) : 0.f;
    }

    const size_t P = (size_t)B_ * L_ * S_;
    *reinterpret_cast<float4*>(out + base)         = make_float4(c01v[0], c01v[1], c01v[2], c01v[3]);
    *reinterpret_cast<float4*>(out + P + base)     = make_float4(c10v[0], c10v[1], c10v[2], c10v[3]);
    *reinterpret_cast<float4*>(out + 2 * P + base) = make_float4(mcv[0],  mcv[1],  mcv[2],  mcv[3]);
}

// ---------------- launch ----------------
extern "C" void kernel_launch(void* const* d_in, const int* in_sizes, int n_in,
                              void* d_out, int out_size)
{
    const float* feat0 = (const float*)d_in[0];
    const float* feat1 = (const float*)d_in[1];
    const float* W     = (const float*)d_in[2];
    const float* bias  = (const float*)d_in[3];
    const int*   h0    = (const int*)d_in[4];
    const int*   w0    = (const int*)d_in[5];
    const int*   h1    = (const int*)d_in[6];
    const int*   w1    = (const int*)d_in[7];
    float* out = (float*)d_out;

    static bool configured = false;
    if (!configured) {
        cudaFuncSetAttribute(sim_kernel,
                             cudaFuncAttributeMaxDynamicSharedMemorySize, DYN_SZ);
        configured = true;
    }

    proj_kernel<<<dim3(2, 75, 1), 256>>>(feat0, W, bias, 0);
    proj_kernel<<<dim3(2, 75, 1), 256>>>(feat1, W, bias, 1);
    sim_kernel<<<dim3(NSPLIT, NT_, B_), 256, DYN_SZ>>>();
    reduce_stats_kernel<<<(2 * BL_ + 255) / 256, 256>>>();
    finalize_kernel<<<(B_ * L_ * (S_ / 4) + 255) / 256, 256>>>(h0, w0, h1, w1, out);
}

// round 6
// speedup vs baseline: 1.9917x; 1.0262x over previous
#include <cuda_runtime.h>
#include <cuda_fp16.h>
#include <cstdint>

#define B_ 2
#define L_ 4800
#define S_ 4800
#define C_ 256
#define NT_ 38          // n-tiles of 128: ceil(4800/128)
#define MT_ 256         // sim m-tile rows
#define NTM_ 19         // ceil(4800/256)
#define UNITS_ (NTM_ * B_ * NT_)   // 19*2*38 = 1444
#define SMPAD 36        // proj kernel smem pad (floats)
#define BL_ (B_ * L_)

// ---- sim kernel smem geometry (fp16) ----
#define ASTRIDE 264                      // halves per A smem row (256 data + 8 pad)
#define HSTRIDE 72                       // halves per B smem row (64 data + 8 pad)
#define ABYTES  (MT_ * ASTRIDE * 2)      // resident A tile: 135168 B
#define BCHUNKB (128 * HSTRIDE * 2)      // one B chunk: 18432 B
#define DYN_SZ  (ABYTES + 2 * BCHUNKB)   // 172032 B

// ---------------- scratch (device globals: no allocs allowed) ----------------
__device__ __half g_f0h[B_ * L_ * C_];
__device__ __half g_f1h[B_ * S_ * C_];
__device__ __half g_simh[(size_t)B_ * L_ * S_];         // E = exp(logit), fp16
__device__ float  g_rmax_p[NT_ * BL_];                  // slot = frag start offset in seg
__device__ float  g_rsum_p[NT_ * BL_];
__device__ float  g_cmax_p[NTM_ * B_ * S_];             // slot = mt
__device__ float  g_csum_p[NTM_ * B_ * S_];
__device__ float  g_rmax[BL_];
__device__ float  g_rsum[BL_];
__device__ float  g_cmax[B_ * S_];
__device__ float  g_csum[B_ * S_];

__device__ __forceinline__ float tf32r(float x) {
    uint32_t u = __float_as_uint(x);
    asm("cvt.rna.tf32.f32 %0, %0;" : "+r"(u));
    return __uint_as_float(u);
}

// tf32 m16n8k8 (proj only)
__device__ __forceinline__ void mma8(float d[4], const uint32_t a[4], const uint32_t b[2]) {
    asm volatile(
        "mma.sync.aligned.m16n8k8.row.col.f32.tf32.tf32.f32 "
        "{%0,%1,%2,%3}, {%4,%5,%6,%7}, {%8,%9}, {%0,%1,%2,%3};"
        : "+f"(d[0]), "+f"(d[1]), "+f"(d[2]), "+f"(d[3])
        : "r"(a[0]), "r"(a[1]), "r"(a[2]), "r"(a[3]), "r"(b[0]), "r"(b[1]));
}

// fp16 m16n8k16 (sim)
__device__ __forceinline__ void mma16(float d[4], uint32_t a0, uint32_t a1,
                                      uint32_t a2, uint32_t a3,
                                      uint32_t b0, uint32_t b1) {
    asm volatile(
        "mma.sync.aligned.m16n8k16.row.col.f32.f16.f16.f32 "
        "{%0,%1,%2,%3}, {%4,%5,%6,%7}, {%8,%9}, {%0,%1,%2,%3};"
        : "+f"(d[0]), "+f"(d[1]), "+f"(d[2]), "+f"(d[3])
        : "r"(a0), "r"(a1), "r"(a2), "r"(a3), "r"(b0), "r"(b1));
}

#define LDSM4(r0, r1, r2, r3, addr)                                            \
    asm volatile("ldmatrix.sync.aligned.m8n8.x4.shared.b16 {%0,%1,%2,%3}, [%4];" \
                 : "=r"(r0), "=r"(r1), "=r"(r2), "=r"(r3) : "r"(addr))

__device__ __forceinline__ float neginf() { return __int_as_float(0xff800000); }

__device__ __forceinline__ uint32_t smaddr(const void* p) {
    return (uint32_t)__cvta_generic_to_shared(p);
}

#define CP16(dst, src, pred)                                                   \
    asm volatile("cp.async.cg.shared.global [%0], [%1], 16, %2;\n" ::          \
                     "r"(dst), "l"(src), "r"((pred) ? 16 : 0))
#define CPCOMMIT() asm volatile("cp.async.commit_group;\n")
#define CPWAIT1()  asm volatile("cp.async.wait_group 1;\n")
#define CPWAIT0()  asm volatile("cp.async.wait_group 0;\n")

// ================= proj: f = fp16((X @ W^T + b) / 16) =================
__device__ __forceinline__ void proj_mainloop(
    const float* __restrict__ A, const float* __restrict__ Bm,
    int m0, int n0, float* As, float* Bs, float acc[4][4][4])
{
    const int tid  = threadIdx.x;
    const int lane = tid & 31;
    const int warp = tid >> 5;
    const int wm = warp >> 2, wn = warp & 3;
    const int gp = lane >> 2, tg = lane & 3;

    for (int kc = 0; kc < C_; kc += 32) {
        #pragma unroll
        for (int i = 0; i < 4; i++) {
            int idx = tid + i * 256;
            int r   = idx >> 3;
            int kq  = (idx & 7) * 4;
            float4 va = *reinterpret_cast<const float4*>(A + (size_t)(m0 + r) * C_ + kc + kq);
            va.x = tf32r(va.x); va.y = tf32r(va.y); va.z = tf32r(va.z); va.w = tf32r(va.w);
            *reinterpret_cast<float4*>(As + r * SMPAD + kq) = va;
            float4 vb = *reinterpret_cast<const float4*>(Bm + (size_t)(n0 + r) * C_ + kc + kq);
            vb.x = tf32r(vb.x); vb.y = tf32r(vb.y); vb.z = tf32r(vb.z); vb.w = tf32r(vb.w);
            *reinterpret_cast<float4*>(Bs + r * SMPAD + kq) = vb;
        }
        __syncthreads();
        #pragma unroll
        for (int ks = 0; ks < 4; ks++) {
            const int k0 = ks * 8;
            uint32_t afr[4][4];
            uint32_t bfr[4][2];
            #pragma unroll
            for (int mf = 0; mf < 4; mf++) {
                const float* p = As + (wm * 64 + mf * 16 + gp) * SMPAD + k0 + tg;
                afr[mf][0] = __float_as_uint(p[0]);
                afr[mf][1] = __float_as_uint(p[8 * SMPAD]);
                afr[mf][2] = __float_as_uint(p[4]);
                afr[mf][3] = __float_as_uint(p[8 * SMPAD + 4]);
            }
            #pragma unroll
            for (int nf = 0; nf < 4; nf++) {
                const float* p = Bs + (wn * 32 + nf * 8 + gp) * SMPAD + k0 + tg;
                bfr[nf][0] = __float_as_uint(p[0]);
                bfr[nf][1] = __float_as_uint(p[4]);
            }
            #pragma unroll
            for (int mf = 0; mf < 4; mf++)
                #pragma unroll
                for (int nf = 0; nf < 4; nf++)
                    mma8(acc[mf][nf], afr[mf], bfr[nf]);
        }
        __syncthreads();
    }
}

__global__ __launch_bounds__(256) void proj_kernel(
    const float* __restrict__ X, const float* __restrict__ W,
    const float* __restrict__ bias, int which)
{
    __shared__ float As[128 * SMPAD];
    __shared__ float Bs[128 * SMPAD];
    float acc[4][4][4] = {};

    const int n0 = blockIdx.x * 128;
    const int m0 = blockIdx.y * 128;
    proj_mainloop(X, W, m0, n0, As, Bs, acc);

    __half* O = which ? g_f1h : g_f0h;
    const int tid = threadIdx.x, lane = tid & 31, warp = tid >> 5;
    const int wm = warp >> 2, wn = warp & 3, gp = lane >> 2, tg = lane & 3;

    #pragma unroll
    for (int mf = 0; mf < 4; mf++) {
        int row = m0 + wm * 64 + mf * 16 + gp;
        #pragma unroll
        for (int nf = 0; nf < 4; nf++) {
            int col = n0 + wn * 32 + nf * 8 + 2 * tg;
            float b0 = __ldg(bias + col), b1 = __ldg(bias + col + 1);
            #pragma unroll
            for (int h = 0; h < 2; h++) {
                __half2 v = __floats2half2_rn(
                    (acc[mf][nf][2 * h]     + b0) * 0.0625f,
                    (acc[mf][nf][2 * h + 1] + b1) * 0.0625f);
                *reinterpret_cast<__half2*>(O + (size_t)(row + 8 * h) * C_ + col) = v;
            }
        }
    }
}

// ======== sim: persistent one-wave, M-tile 256, fp16 E ========
__global__ __launch_bounds__(512, 1) void sim_kernel()
{
    extern __shared__ char dynp[];          // [A tile | B buf0 | B buf1]
    __shared__ float red_m[4 * 256];
    __shared__ float red_s[4 * 256];
    __shared__ float redc_m[4 * 128];
    __shared__ float redc_s[4 * 128];

    const int tid  = threadIdx.x;
    const int lane = tid & 31;
    const int warp = tid >> 5;
    const int wm = warp >> 2, wn = warp & 3;       // 4 x 4 warps
    const int gp = lane >> 2, tg = lane & 3;

    __half* Asm  = (__half*)dynp;
    char*  Bbuf0 = dynp + ABYTES;

    const int ustart = (int)((long long)blockIdx.x * UNITS_ / gridDim.x);
    const int uend   = (int)((long long)(blockIdx.x + 1) * UNITS_ / gridDim.x);

    // ---- loaders ----
    auto load_A = [&](int seg) {
        const int b = seg / NTM_, mt = seg % NTM_;
        const __half* A = g_f0h + (size_t)b * L_ * C_;
        const int m0 = mt * MT_;
        const int r = tid >> 1, hf = tid & 1;
        int gr = m0 + r; bool oa = gr < L_;
        const __half* arow = A + (size_t)(oa ? gr : 0) * C_;
        #pragma unroll
        for (int i = 0; i < 16; i++) {
            int s16 = hf * 16 + i;
            CP16(smaddr(Asm + r * ASTRIDE + s16 * 8), arow + s16 * 8, oa);
        }
    };
    auto load_B = [&](int unit, int cc, int buf) {
        const int seg = unit / NT_, nt = unit % NT_;
        const int b = seg / NTM_;
        const __half* Bm = g_f1h + (size_t)b * S_ * C_;
        __half* Bb = (__half*)(Bbuf0 + buf * BCHUNKB);
        const int kc = cc * 64;
        const int br = tid >> 2, q0 = (tid & 3) * 2;
        int gn = nt * 128 + br; bool ob = gn < S_;
        const __half* brow = Bm + (size_t)(ob ? gn : 0) * C_ + kc;
        #pragma unroll
        for (int q = 0; q < 2; q++) {
            int kk = (q0 + q) * 8;
            CP16(smaddr(Bb + br * HSTRIDE + kk), brow + kk, ob);
        }
    };

    // ldmatrix per-lane offsets (bytes)
    const uint32_t aoff = (uint32_t)((wm * 64 + (lane & 15)) * ASTRIDE + (lane >> 4) * 8) * 2;
    const uint32_t boff = (uint32_t)((wn * 32 + (lane & 7) + ((lane >> 4) & 1) * 8) * HSTRIDE
                                     + ((lane >> 3) & 1) * 8) * 2;
    const uint32_t Abase = smaddr(Asm) + aoff;

    // register-resident row stats for current segment fragment
    float rmx[8], rsm[8];
    #pragma unroll
    for (int i = 0; i < 8; i++) { rmx[i] = neginf(); rsm[i] = 0.f; }

    auto flush_rows = [&](int seg, int frag_start) {
        const int b = seg / NTM_, mt = seg % NTM_;
        const int m0 = mt * MT_;
        const int slot = frag_start - seg * NT_;
        __syncthreads();
        #pragma unroll
        for (int i = 0; i < 8; i++) {
            float m = rmx[i], s = rsm[i];
            m  = fmaxf(m, __shfl_xor_sync(0xffffffffu, m, 1));
            m  = fmaxf(m, __shfl_xor_sync(0xffffffffu, m, 2));
            s += __shfl_xor_sync(0xffffffffu, s, 1);
            s += __shfl_xor_sync(0xffffffffu, s, 2);
            if (tg == 0) {
                int rib = wm * 64 + (i >> 1) * 16 + (i & 1) * 8 + gp;
                red_m[wn * 256 + rib] = m;
                red_s[wn * 256 + rib] = s;
            }
        }
        __syncthreads();
        if (tid < 256) {
            float m = red_m[tid], s = red_s[tid];
            #pragma unroll
            for (int j = 1; j < 4; j++) {
                m = fmaxf(m, red_m[j * 256 + tid]);
                s += red_s[j * 256 + tid];
            }
            int gl = m0 + tid;
            if (gl < L_) {
                size_t o = (size_t)slot * BL_ + b * L_ + gl;
                g_rmax_p[o] = m;
                g_rsum_p[o] = s;
            }
        }
        __syncthreads();
        #pragma unroll
        for (int i = 0; i < 8; i++) { rmx[i] = neginf(); rsm[i] = 0.f; }
    };

    int u = ustart, cur_seg = -1, frag_start = 0, frag_units_end = 0, lc = 0;

    while (u < uend) {
        const int seg = u / NT_;
        if (seg != cur_seg) {
            if (cur_seg >= 0) flush_rows(cur_seg, frag_start);
            CPWAIT0();
            __syncthreads();
            load_A(seg);
            CPCOMMIT();
            load_B(u, 0, 0);
            CPCOMMIT();
            cur_seg = seg;
            frag_start = u;
            frag_units_end = min(uend, (seg + 1) * NT_);
            lc = 0;
        }

        const int b  = seg / NTM_;
        const int mt = seg % NTM_;
        const int m0 = mt * MT_;
        const int n0 = (u % NT_) * 128;

        float acc[4][4][4] = {};

        #pragma unroll
        for (int cc = 0; cc < 4; cc++) {
            const int nl = lc + 1;
            if (nl < (frag_units_end - frag_start) * 4) {
                load_B(frag_start + (nl >> 2), nl & 3, nl & 1);
                CPCOMMIT();
                CPWAIT1();
            } else {
                CPWAIT0();
            }
            __syncthreads();

            const uint32_t Bbase = smaddr(Bbuf0 + (lc & 1) * BCHUNKB) + boff;
            const uint32_t Ac = Abase + (uint32_t)(cc * 64 * 2);

            #pragma unroll
            for (int ks = 0; ks < 4; ks++) {
                const uint32_t kb = (uint32_t)(ks * 16 * 2);
                uint32_t af[4][4];
                uint32_t bf[4][2];
                #pragma unroll
                for (int mf = 0; mf < 4; mf++)
                    LDSM4(af[mf][0], af[mf][1], af[mf][2], af[mf][3],
                          Ac + (uint32_t)(mf * 16 * ASTRIDE * 2) + kb);
                #pragma unroll
                for (int p = 0; p < 2; p++)
                    LDSM4(bf[2 * p][0], bf[2 * p][1], bf[2 * p + 1][0], bf[2 * p + 1][1],
                          Bbase + (uint32_t)(p * 16 * HSTRIDE * 2) + kb);
                #pragma unroll
                for (int mf = 0; mf < 4; mf++)
                    #pragma unroll
                    for (int nf = 0; nf < 4; nf++)
                        mma16(acc[mf][nf], af[mf][0], af[mf][1], af[mf][2], af[mf][3],
                              bf[nf][0], bf[nf][1]);
            }
            __syncthreads();
            lc++;
        }

        // ---- epilogue for unit u ----
        // E = fp16(exp(logit)); stats from the ROUNDED values.
        #pragma unroll
        for (int mf = 0; mf < 4; mf++)
            #pragma unroll
            for (int h = 0; h < 2; h++) {
                int lrow = wm * 64 + mf * 16 + 8 * h + gp;
                int grow = m0 + lrow;
                bool rok = grow < L_;
                float m = rmx[mf * 2 + h], s = rsm[mf * 2 + h];
                #pragma unroll
                for (int nf = 0; nf < 4; nf++) {
                    float ex = __expf(acc[mf][nf][2 * h]     * 10.0f);
                    float ey = __expf(acc[mf][nf][2 * h + 1] * 10.0f);
                    __half2 h2 = __floats2half2_rn(ex, ey);
                    float2 f2 = __half22float2(h2);
                    acc[mf][nf][2 * h]     = f2.x;   // keep rounded for col stats
                    acc[mf][nf][2 * h + 1] = f2.y;
                    int scol = n0 + wn * 32 + nf * 8 + 2 * tg;
                    if (scol < S_) {
                        if (rok)
                            *reinterpret_cast<__half2*>(
                                &g_simh[((size_t)b * L_ + grow) * S_ + scol]) = h2;
                        m = fmaxf(m, fmaxf(f2.x, f2.y));
                        s += f2.x + f2.y;
                    }
                }
                rmx[mf * 2 + h] = m;
                rsm[mf * 2 + h] = s;
            }

        // col partials over this unit's rows (slot = mt)
        #pragma unroll
        for (int nf = 0; nf < 4; nf++)
            #pragma unroll
            for (int ch = 0; ch < 2; ch++) {
                float m = neginf(), s = 0.f;
                #pragma unroll
                for (int mf = 0; mf < 4; mf++)
                    #pragma unroll
                    for (int h = 0; h < 2; h++) {
                        int grow = m0 + wm * 64 + mf * 16 + 8 * h + gp;
                        if (grow < L_) {
                            float v = acc[mf][nf][2 * h + ch];
                            m = fmaxf(m, v);
                            s += v;
                        }
                    }
                m  = fmaxf(m, __shfl_xor_sync(0xffffffffu, m, 4));
                m  = fmaxf(m, __shfl_xor_sync(0xffffffffu, m, 8));
                m  = fmaxf(m, __shfl_xor_sync(0xffffffffu, m, 16));
                s += __shfl_xor_sync(0xffffffffu, s, 4);
                s += __shfl_xor_sync(0xffffffffu, s, 8);
                s += __shfl_xor_sync(0xffffffffu, s, 16);
                if (gp == 0) {
                    int cib = wn * 32 + nf * 8 + 2 * tg + ch;
                    redc_m[wm * 128 + cib] = m;
                    redc_s[wm * 128 + cib] = s;
                }
            }
        __syncthreads();
        if (tid < 128) {
            float m = redc_m[tid], s = redc_s[tid];
            #pragma unroll
            for (int j = 1; j < 4; j++) {
                m = fmaxf(m, redc_m[j * 128 + tid]);
                s += redc_s[j * 128 + tid];
            }
            int gs = n0 + tid;
            if (gs < S_) {
                size_t o = (size_t)mt * (B_ * S_) + b * S_ + gs;
                g_cmax_p[o] = m;
                g_csum_p[o] = s;
            }
        }
        __syncthreads();
        u++;
    }
    flush_rows(cur_seg, frag_start);
}

// ---------------- pass 3: reduce tile partials (coalesced) ----------------
__global__ __launch_bounds__(256) void reduce_stats_kernel()
{
    int i = blockIdx.x * blockDim.x + threadIdx.x;
    if (i < BL_) {
        float m = neginf(), s = 0.f;
        #pragma unroll
        for (int t = 0; t < NT_; t++) {
            m = fmaxf(m, g_rmax_p[(size_t)t * BL_ + i]);
            s += g_rsum_p[(size_t)t * BL_ + i];
        }
        g_rmax[i] = m;
        g_rsum[i] = s;
    } else if (i < 2 * BL_) {
        int j = i - BL_;
        float m = neginf(), s = 0.f;
        #pragma unroll
        for (int t = 0; t < NTM_; t++) {
            m = fmaxf(m, g_cmax_p[(size_t)t * BL_ + j]);
            s += g_csum_p[(size_t)t * BL_ + j];
        }
        g_cmax[j] = m;
        g_csum[j] = s;
    }
}

// ---------------- pass 4: conf planes + mask + mconf ----------------
__global__ __launch_bounds__(256) void finalize_kernel(
    const int* __restrict__ ph0, const int* __restrict__ pw0,
    const int* __restrict__ ph1, const int* __restrict__ pw1,
    float* __restrict__ out)
{
    const int NS4 = S_ / 4;
    int t = blockIdx.x * blockDim.x + threadIdx.x;
    if (t >= B_ * L_ * NS4) return;

    int s0  = (t % NS4) * 4;
    int rem = t / NS4;
    int l   = rem % L_;
    int bb  = rem / L_;

    int h0 = __ldg(ph0), w0 = __ldg(pw0), h1 = __ldg(ph1), w1 = __ldg(pw1);
    int i0 = l / w0, j0 = l - i0 * w0;
    bool in0 = (i0 >= 2) && (i0 < h0 - 2) && (j0 >= 2) && (j0 < w0 - 2);

    size_t base = ((size_t)bb * L_ + l) * S_ + s0;
    __half2 e01 = *reinterpret_cast<const __half2*>(g_simh + base);
    __half2 e23 = *reinterpret_cast<const __half2*>(g_simh + base + 2);
    float2 f01 = __half22float2(e01);
    float2 f23 = __half22float2(e23);

    float rm   = g_rmax[bb * L_ + l];
    float rinv = 1.0f / g_rsum[bb * L_ + l];
    float4 cm4 = *reinterpret_cast<const float4*>(g_cmax + bb * S_ + s0);
    float4 cs4 = *reinterpret_cast<const float4*>(g_csum + bb * S_ + s0);

    float c01v[4], c10v[4], mcv[4];
    const float Es4[4] = {f01.x, f01.y, f23.x, f23.y};
    const float cms[4] = {cm4.x, cm4.y, cm4.z, cm4.w};
    const float css[4] = {cs4.x, cs4.y, cs4.z, cs4.w};

    #pragma unroll
    for (int e = 0; e < 4; e++) {
        int   s   = s0 + e;
        float E   = Es4[e];
        float c01 = E * rinv;
        float c10 = __fdividef(E, css[e]);
        int i1 = s / w1, j1 = s - i1 * w1;
        bool in1 = (i1 >= 2) && (i1 < h1 - 2) && (j1 >= 2) && (j1 < w1 - 2);
        bool mk  = in0 && in1 &&
                   ((c01 > 0.2f && E == rm) || (c10 > 0.2f && E == cms[e]));
        c01v[e] = c01;
        c10v[e] = c10;
        mcv[e]  = mk ? fmaxf(c01, c10) : 0.f;
    }

    const size_t P = (size_t)B_ * L_ * S_;
    *reinterpret_cast<float4*>(out + base)         = make_float4(c01v[0], c01v[1], c01v[2], c01v[3]);
    *reinterpret_cast<float4*>(out + P + base)     = make_float4(c10v[0], c10v[1], c10v[2], c10v[3]);
    *reinterpret_cast<float4*>(out + 2 * P + base) = make_float4(mcv[0],  mcv[1],  mcv[2],  mcv[3]);
}

// ---------------- launch ----------------
extern "C" void kernel_launch(void* const* d_in, const int* in_sizes, int n_in,
                              void* d_out, int out_size)
{
    const float* feat0 = (const float*)d_in[0];
    const float* feat1 = (const float*)d_in[1];
    const float* W     = (const float*)d_in[2];
    const float* bias  = (const float*)d_in[3];
    const int*   h0    = (const int*)d_in[4];
    const int*   w0    = (const int*)d_in[5];
    const int*   h1    = (const int*)d_in[6];
    const int*   w1    = (const int*)d_in[7];
    float* out = (float*)d_out;

    static int nsm = 0;
    if (nsm == 0) {
        cudaDeviceGetAttribute(&nsm, cudaDevAttrMultiProcessorCount, 0);
        if (nsm <= 0) nsm = 148;
        cudaFuncSetAttribute(sim_kernel,
                             cudaFuncAttributeMaxDynamicSharedMemorySize, DYN_SZ);
    }

    proj_kernel<<<dim3(2, 75, 1), 256>>>(feat0, W, bias, 0);
    proj_kernel<<<dim3(2, 75, 1), 256>>>(feat1, W, bias, 1);
    sim_kernel<<<nsm, 512, DYN_SZ>>>();
    reduce_stats_kernel<<<(2 * BL_ + 255) / 256, 256>>>();
    finalize_kernel<<<(B_ * L_ * (S_ / 4) + 255) / 256, 256>>>(h0, w0, h1, w1, out);
}